// round 3
// baseline (speedup 1.0000x reference)
#include <cuda_runtime.h>
#include <math.h>
#include <stdint.h>

#define S_LEN 4096
#define D_MODEL 1024
#define NUM_HEADS 16
#define D_K 64

// ---------------- scratch (no allocs allowed) ----------------
__device__ float g_Q[S_LEN * D_MODEL];
__device__ float g_K[S_LEN * D_MODEL];
__device__ float g_V[S_LEN * D_MODEL];
__device__ float g_AT[S_LEN * D_MODEL];

// ---------------- helpers ----------------
__device__ __forceinline__ float tf32r(float x) {
    uint32_t u;
    asm("cvt.rna.tf32.f32 %0, %1;" : "=r"(u) : "f"(x));
    return __uint_as_float(u);
}
__device__ __forceinline__ uint32_t fau(float x) { return __float_as_uint(x); }

__device__ __forceinline__ void mma_tf32(float* d, const uint32_t* a, uint32_t b0, uint32_t b1) {
    asm volatile(
        "mma.sync.aligned.m16n8k8.row.col.f32.tf32.tf32.f32 "
        "{%0,%1,%2,%3}, {%4,%5,%6,%7}, {%8,%9}, {%0,%1,%2,%3};"
        : "+f"(d[0]), "+f"(d[1]), "+f"(d[2]), "+f"(d[3])
        : "r"(a[0]), "r"(a[1]), "r"(a[2]), "r"(a[3]), "r"(b0), "r"(b1));
}

// split v into tf32 hi/lo interleaved pairs, store 2 float4
__device__ __forceinline__ void sts_split(float* dst, float4 v) {
    float h0 = tf32r(v.x), h1 = tf32r(v.y), h2 = tf32r(v.z), h3 = tf32r(v.w);
    float4 p0 = make_float4(h0, tf32r(v.x - h0), h1, tf32r(v.y - h1));
    float4 p1 = make_float4(h2, tf32r(v.z - h2), h3, tf32r(v.w - h3));
    reinterpret_cast<float4*>(dst)[0] = p0;
    reinterpret_cast<float4*>(dst)[1] = p1;
}

// ============ GEMM v2: C[m,n] = sum_k A[m,k]*W[n,k], 3xTF32, double-buffered ============
// CTA 128x128, BK=16. 8 warps as 2(M) x 4(N): warp tile 64x32.
// smem layout: per row 20 float2 (hi,lo interleaved), 16 used + 4 pad.
#define GP 20                 // float2 pitch per row
#define GSTAGE (128 * GP * 2) // floats per stage per matrix = 5120
#define GEMM_SMEM (4 * GSTAGE * 4)  // bytes = 81920

__global__ __launch_bounds__(256)
void gemm3x_v2(const float* __restrict__ A, const float* __restrict__ W,
               float* __restrict__ C, const int* __restrict__ pos, int rope) {
    extern __shared__ float sm[];
    float* As = sm;
    float* Bs = sm + 2 * GSTAGE;

    const int tid = threadIdx.x;
    const int m0 = blockIdx.y * 128, n0 = blockIdx.x * 128;
    const int w = tid >> 5, lane = tid & 31, g = lane >> 2, t4 = lane & 3;
    const int wm = w & 1, wn = w >> 1;

    const int arow = tid >> 2, ac4 = tid & 3;
    const float* pA0 = A + (size_t)(m0 + arow) * D_MODEL + ac4 * 4;
    const float* pA1 = pA0 + (size_t)64 * D_MODEL;
    const float* pW0 = W + (size_t)(n0 + arow) * D_MODEL + ac4 * 4;
    const float* pW1 = pW0 + (size_t)64 * D_MODEL;
    const int so = arow * (GP * 2) + ac4 * 8;   // float offset in stage

    float acc[4][4][4];
#pragma unroll
    for (int i = 0; i < 4; i++)
#pragma unroll
        for (int j = 0; j < 4; j++)
#pragma unroll
            for (int e = 0; e < 4; e++) acc[i][j][e] = 0.f;

    // prologue: tile 0
    float4 ra0 = *reinterpret_cast<const float4*>(pA0);
    float4 ra1 = *reinterpret_cast<const float4*>(pA1);
    float4 rb0 = *reinterpret_cast<const float4*>(pW0);
    float4 rb1 = *reinterpret_cast<const float4*>(pW1);
    sts_split(As + so, ra0);
    sts_split(As + so + 64 * GP * 2, ra1);
    sts_split(Bs + so, rb0);
    sts_split(Bs + so + 64 * GP * 2, rb1);
    __syncthreads();

    const int NT = D_MODEL / 16;
    for (int t = 0; t < NT; t++) {
        if (t < NT - 1) {
            int k0 = (t + 1) * 16;
            ra0 = *reinterpret_cast<const float4*>(pA0 + k0);
            ra1 = *reinterpret_cast<const float4*>(pA1 + k0);
            rb0 = *reinterpret_cast<const float4*>(pW0 + k0);
            rb1 = *reinterpret_cast<const float4*>(pW1 + k0);
        }
        const float2* A2 = reinterpret_cast<const float2*>(As + (t & 1) * GSTAGE);
        const float2* B2 = reinterpret_cast<const float2*>(Bs + (t & 1) * GSTAGE);
#pragma unroll
        for (int kk = 0; kk < 16; kk += 8) {
            uint32_t ah[4][4], al[4][4];
#pragma unroll
            for (int i = 0; i < 4; i++) {
                int r = (wm * 64 + i * 16 + g) * GP + kk + t4;
                float2 x00 = A2[r], x10 = A2[r + 8 * GP], x01 = A2[r + 4], x11 = A2[r + 8 * GP + 4];
                ah[i][0] = fau(x00.x); ah[i][1] = fau(x10.x); ah[i][2] = fau(x01.x); ah[i][3] = fau(x11.x);
                al[i][0] = fau(x00.y); al[i][1] = fau(x10.y); al[i][2] = fau(x01.y); al[i][3] = fau(x11.y);
            }
#pragma unroll
            for (int j = 0; j < 4; j++) {
                int rb = (wn * 32 + j * 8 + g) * GP + kk + t4;
                float2 b0 = B2[rb], b1 = B2[rb + 4];
                uint32_t bh0 = fau(b0.x), bl0 = fau(b0.y), bh1 = fau(b1.x), bl1 = fau(b1.y);
#pragma unroll
                for (int i = 0; i < 4; i++) {
                    mma_tf32(acc[i][j], ah[i], bh0, bh1);
                    mma_tf32(acc[i][j], ah[i], bl0, bl1);
                    mma_tf32(acc[i][j], al[i], bh0, bh1);
                }
            }
        }
        if (t < NT - 1) {
            float* An = As + ((t + 1) & 1) * GSTAGE;
            float* Bn = Bs + ((t + 1) & 1) * GSTAGE;
            sts_split(An + so, ra0);
            sts_split(An + so + 64 * GP * 2, ra1);
            sts_split(Bn + so, rb0);
            sts_split(Bn + so + 64 * GP * 2, rb1);
            __syncthreads();
        }
    }

    // epilogue (+ optional fused RoPE; adjacent even/odd cols are in-thread)
    float invf[4];
    if (rope) {
#pragma unroll
        for (int j = 0; j < 4; j++) {
            int p = ((wn * 32 + j * 8 + 2 * t4) & 63) >> 1;
            invf[j] = powf(10000.0f, -(float)(2 * p) / (float)D_K);
        }
    }
#pragma unroll
    for (int i = 0; i < 4; i++) {
        int r1 = m0 + wm * 64 + i * 16 + g;
        int r2 = r1 + 8;
        float p1 = 0.f, p2 = 0.f;
        if (rope) { p1 = (float)pos[r1]; p2 = (float)pos[r2]; }
#pragma unroll
        for (int j = 0; j < 4; j++) {
            int c = n0 + wn * 32 + j * 8 + 2 * t4;
            float v0 = acc[i][j][0], v1 = acc[i][j][1];
            float v2 = acc[i][j][2], v3 = acc[i][j][3];
            if (rope) {
                float s, cs;
                sincosf(p1 * invf[j], &s, &cs);
                float u0 = v0 * cs - v1 * s, u1 = v0 * s + v1 * cs;
                v0 = u0; v1 = u1;
                sincosf(p2 * invf[j], &s, &cs);
                float u2 = v2 * cs - v3 * s, u3 = v2 * s + v3 * cs;
                v2 = u2; v3 = u3;
            }
            *reinterpret_cast<float2*>(&C[(size_t)r1 * D_MODEL + c]) = make_float2(v0, v1);
            *reinterpret_cast<float2*>(&C[(size_t)r2 * D_MODEL + c]) = make_float2(v2, v3);
        }
    }
}

// ============ Flash attention with tf32 mma (K hi/lo packed) ============
#define AQ 128
#define AK 64
#define KPITCH 68   // float2 per K row (64 + 4 pad)
#define V_STR  72
#define PS_STR 68
#define ATTN_SMEM ((AK * KPITCH * 2 + AK * V_STR + AQ * PS_STR) * 4)

__global__ __launch_bounds__(256)
void attn_mma_kernel(const float* __restrict__ Q, const float* __restrict__ K,
                     const float* __restrict__ V, float* __restrict__ O) {
    extern __shared__ float sm[];
    float* Kpf = sm;                         // [64][68] float2 (hi,lo)
    float* Vs  = Kpf + AK * KPITCH * 2;      // [64][72]
    float* Ps  = Vs + AK * V_STR;            // [128][68]

    const int h   = blockIdx.y;
    const int q0  = (gridDim.x - 1 - blockIdx.x) * AQ;
    const int tid = threadIdx.x;
    const int w = tid >> 5, lane = tid & 31;
    const int g = lane >> 2, t4 = lane & 3;
    const int wrow = q0 + w * 16;

    // Q fragments (hi/lo), scaled by 1/sqrt(dk)
    uint32_t qh[8][4], ql[8][4];
    {
        const float* qb = Q + (size_t)wrow * D_MODEL + h * D_K;
#pragma unroll
        for (int kc = 0; kc < 8; kc++) {
            int c0 = kc * 8 + t4;
            float v0 = qb[(size_t)g * D_MODEL + c0] * 0.125f;
            float v1 = qb[(size_t)(g + 8) * D_MODEL + c0] * 0.125f;
            float v2 = qb[(size_t)g * D_MODEL + c0 + 4] * 0.125f;
            float v3 = qb[(size_t)(g + 8) * D_MODEL + c0 + 4] * 0.125f;
            float hv;
            hv = tf32r(v0); qh[kc][0] = fau(hv); ql[kc][0] = fau(tf32r(v0 - hv));
            hv = tf32r(v1); qh[kc][1] = fau(hv); ql[kc][1] = fau(tf32r(v1 - hv));
            hv = tf32r(v2); qh[kc][2] = fau(hv); ql[kc][2] = fau(tf32r(v2 - hv));
            hv = tf32r(v3); qh[kc][3] = fau(hv); ql[kc][3] = fau(tf32r(v3 - hv));
        }
    }

    float o[8][4];
#pragma unroll
    for (int j = 0; j < 8; j++)
#pragma unroll
        for (int e = 0; e < 4; e++) o[j][e] = 0.f;
    float m_a = -1e30f, m_b = -1e30f, l_a = 0.f, l_b = 0.f;

    for (int kv0 = 0; kv0 < q0 + AQ; kv0 += AK) {
#pragma unroll
        for (int it = 0; it < 4; it++) {
            int idx = tid + it * 256;
            int r = idx >> 4, c4 = idx & 15;
            float4 kv4 = *reinterpret_cast<const float4*>(
                &K[(size_t)(kv0 + r) * D_MODEL + h * D_K + c4 * 4]);
            sts_split(&Kpf[r * (KPITCH * 2) + c4 * 8], kv4);
            float4 vv = *reinterpret_cast<const float4*>(
                &V[(size_t)(kv0 + r) * D_MODEL + h * D_K + c4 * 4]);
            float4 vh;
            vh.x = tf32r(vv.x); vh.y = tf32r(vv.y); vh.z = tf32r(vv.z); vh.w = tf32r(vv.w);
            *reinterpret_cast<float4*>(&Vs[r * V_STR + c4 * 4]) = vh;
        }
        __syncthreads();

        if (kv0 <= wrow + 15) {
            const float2* K2 = reinterpret_cast<const float2*>(Kpf);
            float s[8][4];
#pragma unroll
            for (int j = 0; j < 8; j++)
#pragma unroll
                for (int e = 0; e < 4; e++) s[j][e] = 0.f;

#pragma unroll
            for (int kc = 0; kc < 8; kc++) {
#pragma unroll
                for (int j = 0; j < 8; j++) {
                    int rb = (j * 8 + g) * KPITCH + kc * 8 + t4;
                    float2 c0 = K2[rb], c1 = K2[rb + 4];
                    mma_tf32(s[j], qh[kc], fau(c0.x), fau(c1.x));
                    mma_tf32(s[j], qh[kc], fau(c0.y), fau(c1.y));
                    mma_tf32(s[j], ql[kc], fau(c0.x), fau(c1.x));
                }
            }

            if (kv0 + AK - 1 > wrow) {
#pragma unroll
                for (int j = 0; j < 8; j++) {
                    int col = kv0 + j * 8 + 2 * t4;
                    int ra = wrow + g, rb2 = wrow + g + 8;
                    if (col > ra)      s[j][0] = -1e30f;
                    if (col + 1 > ra)  s[j][1] = -1e30f;
                    if (col > rb2)     s[j][2] = -1e30f;
                    if (col + 1 > rb2) s[j][3] = -1e30f;
                }
            }

            float mx_a = -1e30f, mx_b = -1e30f;
#pragma unroll
            for (int j = 0; j < 8; j++) {
                mx_a = fmaxf(mx_a, fmaxf(s[j][0], s[j][1]));
                mx_b = fmaxf(mx_b, fmaxf(s[j][2], s[j][3]));
            }
            mx_a = fmaxf(mx_a, __shfl_xor_sync(0xffffffffu, mx_a, 1));
            mx_a = fmaxf(mx_a, __shfl_xor_sync(0xffffffffu, mx_a, 2));
            mx_b = fmaxf(mx_b, __shfl_xor_sync(0xffffffffu, mx_b, 1));
            mx_b = fmaxf(mx_b, __shfl_xor_sync(0xffffffffu, mx_b, 2));
            float nm_a = fmaxf(m_a, mx_a), nm_b = fmaxf(m_b, mx_b);
            float al_a = __expf(m_a - nm_a), al_b = __expf(m_b - nm_b);
            m_a = nm_a; m_b = nm_b;

            float sum_a = 0.f, sum_b = 0.f;
#pragma unroll
            for (int j = 0; j < 8; j++) {
                float p0 = __expf(s[j][0] - m_a);
                float p1 = __expf(s[j][1] - m_a);
                float p2 = __expf(s[j][2] - m_b);
                float p3 = __expf(s[j][3] - m_b);
                sum_a += p0 + p1;
                sum_b += p2 + p3;
                o[j][0] *= al_a; o[j][1] *= al_a;
                o[j][2] *= al_b; o[j][3] *= al_b;
                float2 pa = make_float2(tf32r(p0), tf32r(p1));
                float2 pb = make_float2(tf32r(p2), tf32r(p3));
                *reinterpret_cast<float2*>(&Ps[(w * 16 + g) * PS_STR + j * 8 + 2 * t4]) = pa;
                *reinterpret_cast<float2*>(&Ps[(w * 16 + g + 8) * PS_STR + j * 8 + 2 * t4]) = pb;
            }
            sum_a += __shfl_xor_sync(0xffffffffu, sum_a, 1);
            sum_a += __shfl_xor_sync(0xffffffffu, sum_a, 2);
            sum_b += __shfl_xor_sync(0xffffffffu, sum_b, 1);
            sum_b += __shfl_xor_sync(0xffffffffu, sum_b, 2);
            l_a = l_a * al_a + sum_a;
            l_b = l_b * al_b + sum_b;
            __syncwarp();

#pragma unroll
            for (int kc = 0; kc < 8; kc++) {
                uint32_t pa[4];
                int pr = (w * 16 + g) * PS_STR + kc * 8 + t4;
                pa[0] = fau(Ps[pr]);
                pa[1] = fau(Ps[pr + 8 * PS_STR]);
                pa[2] = fau(Ps[pr + 4]);
                pa[3] = fau(Ps[pr + 8 * PS_STR + 4]);
#pragma unroll
                for (int j = 0; j < 8; j++) {
                    int vb = (kc * 8 + t4) * V_STR + j * 8 + g;
                    uint32_t b0 = fau(Vs[vb]);
                    uint32_t b1 = fau(Vs[vb + 4 * V_STR]);
                    mma_tf32(o[j], pa, b0, b1);
                }
            }
        }
        __syncthreads();
    }

    float ia = 1.0f / l_a, ib = 1.0f / l_b;
#pragma unroll
    for (int j = 0; j < 8; j++) {
        int c = h * D_K + j * 8 + 2 * t4;
        float2 v0 = make_float2(o[j][0] * ia, o[j][1] * ia);
        float2 v1 = make_float2(o[j][2] * ib, o[j][3] * ib);
        *reinterpret_cast<float2*>(&O[(size_t)(wrow + g) * D_MODEL + c]) = v0;
        *reinterpret_cast<float2*>(&O[(size_t)(wrow + g + 8) * D_MODEL + c]) = v1;
    }
}

// ---------------- launcher ----------------
extern "C" void kernel_launch(void* const* d_in, const int* in_sizes, int n_in,
                              void* d_out, int out_size) {
    const float* x  = (const float*)d_in[0];
    const float* Wq = (const float*)d_in[1];
    const float* Wk = (const float*)d_in[2];
    const float* Wv = (const float*)d_in[3];
    const float* Wo = (const float*)d_in[4];
    const int*  pos = (const int*)d_in[5];
    float* out = (float*)d_out;

    float *Qp, *Kp, *Vp, *Ap;
    cudaGetSymbolAddress((void**)&Qp, g_Q);
    cudaGetSymbolAddress((void**)&Kp, g_K);
    cudaGetSymbolAddress((void**)&Vp, g_V);
    cudaGetSymbolAddress((void**)&Ap, g_AT);

    cudaFuncSetAttribute(gemm3x_v2, cudaFuncAttributeMaxDynamicSharedMemorySize, GEMM_SMEM);
    cudaFuncSetAttribute(attn_mma_kernel, cudaFuncAttributeMaxDynamicSharedMemorySize, ATTN_SMEM);

    dim3 ggrid(D_MODEL / 128, S_LEN / 128);   // (8, 32)
    gemm3x_v2<<<ggrid, 256, GEMM_SMEM>>>(x, Wq, Qp, pos, 1);
    gemm3x_v2<<<ggrid, 256, GEMM_SMEM>>>(x, Wk, Kp, pos, 1);
    gemm3x_v2<<<ggrid, 256, GEMM_SMEM>>>(x, Wv, Vp, pos, 0);

    dim3 agrid(S_LEN / AQ, NUM_HEADS);        // (32, 16)
    attn_mma_kernel<<<agrid, 256, ATTN_SMEM>>>(Qp, Kp, Vp, Ap);

    gemm3x_v2<<<ggrid, 256, GEMM_SMEM>>>(Ap, Wo, out, pos, 0);
}

// round 4
// speedup vs baseline: 1.1687x; 1.1687x over previous
#include <cuda_runtime.h>
#include <math.h>
#include <stdint.h>

#define S_LEN 4096
#define D_MODEL 1024
#define NUM_HEADS 16
#define D_K 64

// ---------------- scratch (no allocs allowed) ----------------
__device__ float g_Q[S_LEN * D_MODEL];
__device__ float g_K[S_LEN * D_MODEL];
__device__ float g_V[S_LEN * D_MODEL];
__device__ float g_AT[S_LEN * D_MODEL];

// ---------------- helpers ----------------
__device__ __forceinline__ float tf32r(float x) {
    uint32_t u;
    asm("cvt.rna.tf32.f32 %0, %1;" : "=r"(u) : "f"(x));
    return __uint_as_float(u);
}
__device__ __forceinline__ uint32_t fau(float x) { return __float_as_uint(x); }

__device__ __forceinline__ void mma_tf32(float* d, const uint32_t* a, uint32_t b0, uint32_t b1) {
    asm volatile(
        "mma.sync.aligned.m16n8k8.row.col.f32.tf32.tf32.f32 "
        "{%0,%1,%2,%3}, {%4,%5,%6,%7}, {%8,%9}, {%0,%1,%2,%3};"
        : "+f"(d[0]), "+f"(d[1]), "+f"(d[2]), "+f"(d[3])
        : "r"(a[0]), "r"(a[1]), "r"(a[2]), "r"(a[3]), "r"(b0), "r"(b1));
}

// split v into tf32 hi/lo interleaved pairs, store 2 float4
__device__ __forceinline__ void sts_split(float* dst, float4 v) {
    float h0 = tf32r(v.x), h1 = tf32r(v.y), h2 = tf32r(v.z), h3 = tf32r(v.w);
    float4 p0 = make_float4(h0, tf32r(v.x - h0), h1, tf32r(v.y - h1));
    float4 p1 = make_float4(h2, tf32r(v.z - h2), h3, tf32r(v.w - h3));
    reinterpret_cast<float4*>(dst)[0] = p0;
    reinterpret_cast<float4*>(dst)[1] = p1;
}

// ---------------- 3xTF32 GEMM (R2-proven): C[m,n] = sum_k A[m,k]*B[n,k] ----------------
#define GBM 128
#define GBN 128
#define GBK 16
#define G_STR 20

__global__ __launch_bounds__(256)
void gemm3x_kernel(const float* __restrict__ A, const float* __restrict__ B,
                   float* __restrict__ C, int M, int N, int K,
                   const int* __restrict__ pos, int rope) {
    __shared__ float Ash[GBM * G_STR];
    __shared__ float Asl[GBM * G_STR];
    __shared__ float Bsh[GBN * G_STR];
    __shared__ float Bsl[GBN * G_STR];

    const int tid = threadIdx.x;
    const int m0 = blockIdx.y * GBM;
    const int n0 = blockIdx.x * GBN;
    const int w = tid >> 5, lane = tid & 31;
    const int g = lane >> 2, t4 = lane & 3;
    const int wm = w >> 1, wn = w & 1;     // 4x2 warp grid, warp tile 32x64

    float acc[2][8][4];
#pragma unroll
    for (int i = 0; i < 2; i++)
#pragma unroll
        for (int j = 0; j < 8; j++)
#pragma unroll
            for (int e = 0; e < 4; e++) acc[i][j][e] = 0.f;

    for (int k0 = 0; k0 < K; k0 += GBK) {
#pragma unroll
        for (int it = 0; it < 2; it++) {
            int idx = tid + it * 256;        // float4 index: 512 per tile
            int row = idx >> 2;
            int c4  = idx & 3;
            float4 va = *reinterpret_cast<const float4*>(&A[(size_t)(m0 + row) * K + k0 + c4 * 4]);
            float4 hi, lo;
            hi.x = tf32r(va.x); lo.x = tf32r(va.x - hi.x);
            hi.y = tf32r(va.y); lo.y = tf32r(va.y - hi.y);
            hi.z = tf32r(va.z); lo.z = tf32r(va.z - hi.z);
            hi.w = tf32r(va.w); lo.w = tf32r(va.w - hi.w);
            *reinterpret_cast<float4*>(&Ash[row * G_STR + c4 * 4]) = hi;
            *reinterpret_cast<float4*>(&Asl[row * G_STR + c4 * 4]) = lo;
            float4 vb = *reinterpret_cast<const float4*>(&B[(size_t)(n0 + row) * K + k0 + c4 * 4]);
            hi.x = tf32r(vb.x); lo.x = tf32r(vb.x - hi.x);
            hi.y = tf32r(vb.y); lo.y = tf32r(vb.y - hi.y);
            hi.z = tf32r(vb.z); lo.z = tf32r(vb.z - hi.z);
            hi.w = tf32r(vb.w); lo.w = tf32r(vb.w - hi.w);
            *reinterpret_cast<float4*>(&Bsh[row * G_STR + c4 * 4]) = hi;
            *reinterpret_cast<float4*>(&Bsl[row * G_STR + c4 * 4]) = lo;
        }
        __syncthreads();

#pragma unroll
        for (int kk = 0; kk < GBK; kk += 8) {
            uint32_t ah[2][4], al[2][4];
#pragma unroll
            for (int i = 0; i < 2; i++) {
                int r = (wm * 32 + i * 16 + g) * G_STR + kk + t4;
                ah[i][0] = fau(Ash[r]);
                ah[i][1] = fau(Ash[r + 8 * G_STR]);
                ah[i][2] = fau(Ash[r + 4]);
                ah[i][3] = fau(Ash[r + 8 * G_STR + 4]);
                al[i][0] = fau(Asl[r]);
                al[i][1] = fau(Asl[r + 8 * G_STR]);
                al[i][2] = fau(Asl[r + 4]);
                al[i][3] = fau(Asl[r + 8 * G_STR + 4]);
            }
#pragma unroll
            for (int j = 0; j < 8; j++) {
                int rb = (wn * 64 + j * 8 + g) * G_STR + kk + t4;
                uint32_t bh0 = fau(Bsh[rb]);
                uint32_t bh1 = fau(Bsh[rb + 4]);
                uint32_t bl0 = fau(Bsl[rb]);
                uint32_t bl1 = fau(Bsl[rb + 4]);
#pragma unroll
                for (int i = 0; i < 2; i++) {
                    mma_tf32(acc[i][j], ah[i], bh0, bh1);
                    mma_tf32(acc[i][j], ah[i], bl0, bl1);
                    mma_tf32(acc[i][j], al[i], bh0, bh1);
                }
            }
        }
        __syncthreads();
    }

    // epilogue, optionally with fused RoPE (adjacent even/odd cols are in-thread)
    float invf[8];
    if (rope) {
#pragma unroll
        for (int j = 0; j < 8; j++) {
            int p = ((wn * 64 + j * 8 + 2 * t4) & 63) >> 1;
            invf[j] = powf(10000.0f, -(float)(2 * p) / (float)D_K);
        }
    }
#pragma unroll
    for (int i = 0; i < 2; i++) {
        int r1 = m0 + wm * 32 + i * 16 + g;
        int r2 = r1 + 8;
        float p1 = 0.f, p2 = 0.f;
        if (rope) { p1 = (float)pos[r1]; p2 = (float)pos[r2]; }
#pragma unroll
        for (int j = 0; j < 8; j++) {
            int c = n0 + wn * 64 + j * 8 + 2 * t4;
            float v0 = acc[i][j][0], v1 = acc[i][j][1];
            float v2 = acc[i][j][2], v3 = acc[i][j][3];
            if (rope) {
                float s, cs;
                sincosf(p1 * invf[j], &s, &cs);
                float u0 = v0 * cs - v1 * s, u1 = v0 * s + v1 * cs;
                v0 = u0; v1 = u1;
                sincosf(p2 * invf[j], &s, &cs);
                float u2 = v2 * cs - v3 * s, u3 = v2 * s + v3 * cs;
                v2 = u2; v3 = u3;
            }
            *reinterpret_cast<float2*>(&C[(size_t)r1 * N + c]) = make_float2(v0, v1);
            *reinterpret_cast<float2*>(&C[(size_t)r2 * N + c]) = make_float2(v2, v3);
        }
    }
}

// ============ Flash attention, tf32 mma, 2 CTAs/SM ============
// QK: qh*(Khi + Klo)  (Q rounded to tf32; K error-compensated)
// PV: 1x tf32
#define AQ 128
#define AK 64
#define KPITCH 68   // float2 per K row (64 + 4 pad)
#define V_STR  72
#define PS_STR 68
#define ATTN_SMEM ((AK * KPITCH * 2 + AK * V_STR + AQ * PS_STR) * 4)

__global__ __launch_bounds__(256, 2)
void attn_mma_kernel(const float* __restrict__ Q, const float* __restrict__ K,
                     const float* __restrict__ V, float* __restrict__ O) {
    extern __shared__ float sm[];
    float* Kpf = sm;                         // [64][68] float2 (hi,lo)
    float* Vs  = Kpf + AK * KPITCH * 2;      // [64][72]
    float* Ps  = Vs + AK * V_STR;            // [128][68]

    const int h   = blockIdx.y;
    const int q0  = (gridDim.x - 1 - blockIdx.x) * AQ;  // big CTAs first
    const int tid = threadIdx.x;
    const int w = tid >> 5, lane = tid & 31;
    const int g = lane >> 2, t4 = lane & 3;
    const int wrow = q0 + w * 16;

    // Q fragments (tf32), scaled by 1/sqrt(dk)
    uint32_t qh[8][4];
    {
        const float* qb = Q + (size_t)wrow * D_MODEL + h * D_K;
#pragma unroll
        for (int kc = 0; kc < 8; kc++) {
            int c0 = kc * 8 + t4;
            qh[kc][0] = fau(tf32r(qb[(size_t)g * D_MODEL + c0] * 0.125f));
            qh[kc][1] = fau(tf32r(qb[(size_t)(g + 8) * D_MODEL + c0] * 0.125f));
            qh[kc][2] = fau(tf32r(qb[(size_t)g * D_MODEL + c0 + 4] * 0.125f));
            qh[kc][3] = fau(tf32r(qb[(size_t)(g + 8) * D_MODEL + c0 + 4] * 0.125f));
        }
    }

    float o[8][4];
#pragma unroll
    for (int j = 0; j < 8; j++)
#pragma unroll
        for (int e = 0; e < 4; e++) o[j][e] = 0.f;
    float m_a = -1e30f, m_b = -1e30f, l_a = 0.f, l_b = 0.f;

    for (int kv0 = 0; kv0 < q0 + AQ; kv0 += AK) {
#pragma unroll
        for (int it = 0; it < 4; it++) {
            int idx = tid + it * 256;
            int r = idx >> 4, c4 = idx & 15;
            float4 kv4 = *reinterpret_cast<const float4*>(
                &K[(size_t)(kv0 + r) * D_MODEL + h * D_K + c4 * 4]);
            sts_split(&Kpf[r * (KPITCH * 2) + c4 * 8], kv4);
            float4 vv = *reinterpret_cast<const float4*>(
                &V[(size_t)(kv0 + r) * D_MODEL + h * D_K + c4 * 4]);
            float4 vh;
            vh.x = tf32r(vv.x); vh.y = tf32r(vv.y); vh.z = tf32r(vv.z); vh.w = tf32r(vv.w);
            *reinterpret_cast<float4*>(&Vs[r * V_STR + c4 * 4]) = vh;
        }
        __syncthreads();

        if (kv0 <= wrow + 15) {
            const float2* K2 = reinterpret_cast<const float2*>(Kpf);
            float s[8][4];
#pragma unroll
            for (int j = 0; j < 8; j++)
#pragma unroll
                for (int e = 0; e < 4; e++) s[j][e] = 0.f;

#pragma unroll
            for (int kc = 0; kc < 8; kc++) {
#pragma unroll
                for (int j = 0; j < 8; j++) {
                    int rb = (j * 8 + g) * KPITCH + kc * 8 + t4;
                    float2 c0 = K2[rb], c1 = K2[rb + 4];
                    mma_tf32(s[j], qh[kc], fau(c0.x), fau(c1.x));
                    mma_tf32(s[j], qh[kc], fau(c0.y), fau(c1.y));
                }
            }

            if (kv0 + AK - 1 > wrow) {   // diagonal tile: causal mask
#pragma unroll
                for (int j = 0; j < 8; j++) {
                    int col = kv0 + j * 8 + 2 * t4;
                    int ra = wrow + g, rb2 = wrow + g + 8;
                    if (col > ra)      s[j][0] = -1e30f;
                    if (col + 1 > ra)  s[j][1] = -1e30f;
                    if (col > rb2)     s[j][2] = -1e30f;
                    if (col + 1 > rb2) s[j][3] = -1e30f;
                }
            }

            float mx_a = -1e30f, mx_b = -1e30f;
#pragma unroll
            for (int j = 0; j < 8; j++) {
                mx_a = fmaxf(mx_a, fmaxf(s[j][0], s[j][1]));
                mx_b = fmaxf(mx_b, fmaxf(s[j][2], s[j][3]));
            }
            mx_a = fmaxf(mx_a, __shfl_xor_sync(0xffffffffu, mx_a, 1));
            mx_a = fmaxf(mx_a, __shfl_xor_sync(0xffffffffu, mx_a, 2));
            mx_b = fmaxf(mx_b, __shfl_xor_sync(0xffffffffu, mx_b, 1));
            mx_b = fmaxf(mx_b, __shfl_xor_sync(0xffffffffu, mx_b, 2));
            float nm_a = fmaxf(m_a, mx_a), nm_b = fmaxf(m_b, mx_b);
            float al_a = __expf(m_a - nm_a), al_b = __expf(m_b - nm_b);
            m_a = nm_a; m_b = nm_b;

            float sum_a = 0.f, sum_b = 0.f;
#pragma unroll
            for (int j = 0; j < 8; j++) {
                float p0 = __expf(s[j][0] - m_a);
                float p1 = __expf(s[j][1] - m_a);
                float p2 = __expf(s[j][2] - m_b);
                float p3 = __expf(s[j][3] - m_b);
                sum_a += p0 + p1;
                sum_b += p2 + p3;
                o[j][0] *= al_a; o[j][1] *= al_a;
                o[j][2] *= al_b; o[j][3] *= al_b;
                float2 pa = make_float2(tf32r(p0), tf32r(p1));
                float2 pb = make_float2(tf32r(p2), tf32r(p3));
                *reinterpret_cast<float2*>(&Ps[(w * 16 + g) * PS_STR + j * 8 + 2 * t4]) = pa;
                *reinterpret_cast<float2*>(&Ps[(w * 16 + g + 8) * PS_STR + j * 8 + 2 * t4]) = pb;
            }
            sum_a += __shfl_xor_sync(0xffffffffu, sum_a, 1);
            sum_a += __shfl_xor_sync(0xffffffffu, sum_a, 2);
            sum_b += __shfl_xor_sync(0xffffffffu, sum_b, 1);
            sum_b += __shfl_xor_sync(0xffffffffu, sum_b, 2);
            l_a = l_a * al_a + sum_a;
            l_b = l_b * al_b + sum_b;
            __syncwarp();

#pragma unroll
            for (int kc = 0; kc < 8; kc++) {
                uint32_t pa[4];
                int pr = (w * 16 + g) * PS_STR + kc * 8 + t4;
                pa[0] = fau(Ps[pr]);
                pa[1] = fau(Ps[pr + 8 * PS_STR]);
                pa[2] = fau(Ps[pr + 4]);
                pa[3] = fau(Ps[pr + 8 * PS_STR + 4]);
#pragma unroll
                for (int j = 0; j < 8; j++) {
                    int vb = (kc * 8 + t4) * V_STR + j * 8 + g;
                    uint32_t b0 = fau(Vs[vb]);
                    uint32_t b1 = fau(Vs[vb + 4 * V_STR]);
                    mma_tf32(o[j], pa, b0, b1);
                }
            }
        }
        __syncthreads();
    }

    float ia = 1.0f / l_a, ib = 1.0f / l_b;
#pragma unroll
    for (int j = 0; j < 8; j++) {
        int c = h * D_K + j * 8 + 2 * t4;
        float2 v0 = make_float2(o[j][0] * ia, o[j][1] * ia);
        float2 v1 = make_float2(o[j][2] * ib, o[j][3] * ib);
        *reinterpret_cast<float2*>(&O[(size_t)(wrow + g) * D_MODEL + c]) = v0;
        *reinterpret_cast<float2*>(&O[(size_t)(wrow + g + 8) * D_MODEL + c]) = v1;
    }
}

// ---------------- launcher ----------------
extern "C" void kernel_launch(void* const* d_in, const int* in_sizes, int n_in,
                              void* d_out, int out_size) {
    const float* x  = (const float*)d_in[0];
    const float* Wq = (const float*)d_in[1];
    const float* Wk = (const float*)d_in[2];
    const float* Wv = (const float*)d_in[3];
    const float* Wo = (const float*)d_in[4];
    const int*  pos = (const int*)d_in[5];
    float* out = (float*)d_out;

    float *Qp, *Kp, *Vp, *Ap;
    cudaGetSymbolAddress((void**)&Qp, g_Q);
    cudaGetSymbolAddress((void**)&Kp, g_K);
    cudaGetSymbolAddress((void**)&Vp, g_V);
    cudaGetSymbolAddress((void**)&Ap, g_AT);

    cudaFuncSetAttribute(attn_mma_kernel, cudaFuncAttributeMaxDynamicSharedMemorySize, ATTN_SMEM);

    dim3 ggrid(D_MODEL / GBN, S_LEN / GBM);   // (8, 32)
    gemm3x_kernel<<<ggrid, 256>>>(x, Wq, Qp, S_LEN, D_MODEL, D_MODEL, pos, 1);
    gemm3x_kernel<<<ggrid, 256>>>(x, Wk, Kp, S_LEN, D_MODEL, D_MODEL, pos, 1);
    gemm3x_kernel<<<ggrid, 256>>>(x, Wv, Vp, S_LEN, D_MODEL, D_MODEL, pos, 0);

    dim3 agrid(S_LEN / AQ, NUM_HEADS);        // (32, 16)
    attn_mma_kernel<<<agrid, 256, ATTN_SMEM>>>(Qp, Kp, Vp, Ap);

    gemm3x_kernel<<<ggrid, 256>>>(Ap, Wo, out, S_LEN, D_MODEL, D_MODEL, pos, 0);
}

// round 6
// speedup vs baseline: 1.3823x; 1.1827x over previous
#include <cuda_runtime.h>
#include <math.h>
#include <stdint.h>

#define S_LEN 4096
#define D_MODEL 1024
#define NUM_HEADS 16
#define D_K 64

// ---------------- scratch (no allocs allowed) ----------------
__device__ float g_Q[S_LEN * D_MODEL];
__device__ float g_K[S_LEN * D_MODEL];
__device__ float g_V[S_LEN * D_MODEL];
__device__ float g_AT[S_LEN * D_MODEL];

// ---------------- helpers ----------------
__device__ __forceinline__ float tf32r(float x) {
    uint32_t u;
    asm("cvt.rna.tf32.f32 %0, %1;" : "=r"(u) : "f"(x));
    return __uint_as_float(u);
}
__device__ __forceinline__ uint32_t fau(float x) { return __float_as_uint(x); }

__device__ __forceinline__ void mma_tf32(float* d, const uint32_t* a, uint32_t b0, uint32_t b1) {
    asm volatile(
        "mma.sync.aligned.m16n8k8.row.col.f32.tf32.tf32.f32 "
        "{%0,%1,%2,%3}, {%4,%5,%6,%7}, {%8,%9}, {%0,%1,%2,%3};"
        : "+f"(d[0]), "+f"(d[1]), "+f"(d[2]), "+f"(d[3])
        : "r"(a[0]), "r"(a[1]), "r"(a[2]), "r"(a[3]), "r"(b0), "r"(b1));
}

// ---------------- 3xTF32 GEMM: C[m,n] = sum_k A[m,k]*B[n,k] ----------------
#define GBM 128
#define GBN 128
#define GBK 16
#define G_STR 20

template<int ROPE>
__global__ __launch_bounds__(256)
void gemm3x_kernel(const float* __restrict__ A, const float* __restrict__ B,
                   float* __restrict__ C, int M, int N, int K,
                   const int* __restrict__ pos) {
    __shared__ float Ash[GBM * G_STR];
    __shared__ float Asl[GBM * G_STR];
    __shared__ float Bsh[GBN * G_STR];
    __shared__ float Bsl[GBN * G_STR];

    const int tid = threadIdx.x;
    const int m0 = blockIdx.y * GBM;
    const int n0 = blockIdx.x * GBN;
    const int w = tid >> 5, lane = tid & 31;
    const int g = lane >> 2, t4 = lane & 3;
    const int wm = w >> 1, wn = w & 1;     // 4x2 warp grid, warp tile 32x64

    float acc[2][8][4];
#pragma unroll
    for (int i = 0; i < 2; i++)
#pragma unroll
        for (int j = 0; j < 8; j++)
#pragma unroll
            for (int e = 0; e < 4; e++) acc[i][j][e] = 0.f;

    for (int k0 = 0; k0 < K; k0 += GBK) {
#pragma unroll
        for (int it = 0; it < 2; it++) {
            int idx = tid + it * 256;        // float4 index: 512 per tile
            int row = idx >> 2;
            int c4  = idx & 3;
            float4 va = *reinterpret_cast<const float4*>(&A[(size_t)(m0 + row) * K + k0 + c4 * 4]);
            float4 hi, lo;
            hi.x = tf32r(va.x); lo.x = tf32r(va.x - hi.x);
            hi.y = tf32r(va.y); lo.y = tf32r(va.y - hi.y);
            hi.z = tf32r(va.z); lo.z = tf32r(va.z - hi.z);
            hi.w = tf32r(va.w); lo.w = tf32r(va.w - hi.w);
            *reinterpret_cast<float4*>(&Ash[row * G_STR + c4 * 4]) = hi;
            *reinterpret_cast<float4*>(&Asl[row * G_STR + c4 * 4]) = lo;
            float4 vb = *reinterpret_cast<const float4*>(&B[(size_t)(n0 + row) * K + k0 + c4 * 4]);
            hi.x = tf32r(vb.x); lo.x = tf32r(vb.x - hi.x);
            hi.y = tf32r(vb.y); lo.y = tf32r(vb.y - hi.y);
            hi.z = tf32r(vb.z); lo.z = tf32r(vb.z - hi.z);
            hi.w = tf32r(vb.w); lo.w = tf32r(vb.w - hi.w);
            *reinterpret_cast<float4*>(&Bsh[row * G_STR + c4 * 4]) = hi;
            *reinterpret_cast<float4*>(&Bsl[row * G_STR + c4 * 4]) = lo;
        }
        __syncthreads();

#pragma unroll
        for (int kk = 0; kk < GBK; kk += 8) {
            uint32_t ah[2][4], al[2][4];
#pragma unroll
            for (int i = 0; i < 2; i++) {
                int r = (wm * 32 + i * 16 + g) * G_STR + kk + t4;
                ah[i][0] = fau(Ash[r]);
                ah[i][1] = fau(Ash[r + 8 * G_STR]);
                ah[i][2] = fau(Ash[r + 4]);
                ah[i][3] = fau(Ash[r + 8 * G_STR + 4]);
                al[i][0] = fau(Asl[r]);
                al[i][1] = fau(Asl[r + 8 * G_STR]);
                al[i][2] = fau(Asl[r + 4]);
                al[i][3] = fau(Asl[r + 8 * G_STR + 4]);
            }
#pragma unroll
            for (int j = 0; j < 8; j++) {
                int rb = (wn * 64 + j * 8 + g) * G_STR + kk + t4;
                uint32_t bh0 = fau(Bsh[rb]);
                uint32_t bh1 = fau(Bsh[rb + 4]);
                uint32_t bl0 = fau(Bsl[rb]);
                uint32_t bl1 = fau(Bsl[rb + 4]);
#pragma unroll
                for (int i = 0; i < 2; i++) {
                    mma_tf32(acc[i][j], ah[i], bh0, bh1);
                    mma_tf32(acc[i][j], ah[i], bl0, bl1);
                    mma_tf32(acc[i][j], al[i], bh0, bh1);
                }
            }
        }
        __syncthreads();
    }

    // epilogue; ROPE is compile-time
    float invf[8];
    if (ROPE) {
#pragma unroll
        for (int j = 0; j < 8; j++) {
            int p = ((wn * 64 + j * 8 + 2 * t4) & 63) >> 1;
            invf[j] = powf(10000.0f, -(float)(2 * p) / (float)D_K);
        }
    }
#pragma unroll
    for (int i = 0; i < 2; i++) {
        int r1 = m0 + wm * 32 + i * 16 + g;
        int r2 = r1 + 8;
        float p1 = 0.f, p2 = 0.f;
        if (ROPE) { p1 = (float)pos[r1]; p2 = (float)pos[r2]; }
#pragma unroll
        for (int j = 0; j < 8; j++) {
            int c = n0 + wn * 64 + j * 8 + 2 * t4;
            float v0 = acc[i][j][0], v1 = acc[i][j][1];
            float v2 = acc[i][j][2], v3 = acc[i][j][3];
            if (ROPE) {
                float s, cs;
                sincosf(p1 * invf[j], &s, &cs);
                float u0 = v0 * cs - v1 * s, u1 = v0 * s + v1 * cs;
                v0 = u0; v1 = u1;
                sincosf(p2 * invf[j], &s, &cs);
                float u2 = v2 * cs - v3 * s, u3 = v2 * s + v3 * cs;
                v2 = u2; v3 = u3;
            }
            *reinterpret_cast<float2*>(&C[(size_t)r1 * N + c]) = make_float2(v0, v1);
            *reinterpret_cast<float2*>(&C[(size_t)r2 * N + c]) = make_float2(v2, v3);
        }
    }
}

// ============ Flash attention, tf32 mma, 2 CTAs/SM ============
// QK: pure tf32 (Q and K rounded rna to tf32). PV: tf32.
#define AQ 128
#define AK 64
#define KS_STR 68   // floats per K row (64 + 4 pad); 68 mod 32 = 4 -> conflict-free frags
#define V_STR  72
#define PS_STR 68
#define ATTN_SMEM ((AK * KS_STR + AK * V_STR + AQ * PS_STR) * 4)

__global__ __launch_bounds__(256, 2)
void attn_mma_kernel(const float* __restrict__ Q, const float* __restrict__ K,
                     const float* __restrict__ V, float* __restrict__ O) {
    extern __shared__ float sm[];
    float* Ks = sm;                      // [64][68] tf32
    float* Vs = Ks + AK * KS_STR;        // [64][72] tf32
    float* Ps = Vs + AK * V_STR;         // [128][68] tf32

    const int h   = blockIdx.y;
    const int q0  = (gridDim.x - 1 - blockIdx.x) * AQ;  // big CTAs first
    const int tid = threadIdx.x;
    const int w = tid >> 5, lane = tid & 31;
    const int g = lane >> 2, t4 = lane & 3;
    const int wrow = q0 + w * 16;

    // Q fragments (tf32), scaled by 1/sqrt(dk)
    uint32_t qh[8][4];
    {
        const float* qb = Q + (size_t)wrow * D_MODEL + h * D_K;
#pragma unroll
        for (int kc = 0; kc < 8; kc++) {
            int c0 = kc * 8 + t4;
            qh[kc][0] = fau(tf32r(qb[(size_t)g * D_MODEL + c0] * 0.125f));
            qh[kc][1] = fau(tf32r(qb[(size_t)(g + 8) * D_MODEL + c0] * 0.125f));
            qh[kc][2] = fau(tf32r(qb[(size_t)g * D_MODEL + c0 + 4] * 0.125f));
            qh[kc][3] = fau(tf32r(qb[(size_t)(g + 8) * D_MODEL + c0 + 4] * 0.125f));
        }
    }

    float o[8][4];
#pragma unroll
    for (int j = 0; j < 8; j++)
#pragma unroll
        for (int e = 0; e < 4; e++) o[j][e] = 0.f;
    float m_a = -1e30f, m_b = -1e30f, l_a = 0.f, l_b = 0.f;

    for (int kv0 = 0; kv0 < q0 + AQ; kv0 += AK) {
#pragma unroll
        for (int it = 0; it < 4; it++) {
            int idx = tid + it * 256;
            int r = idx >> 4, c4 = idx & 15;
            float4 kv4 = *reinterpret_cast<const float4*>(
                &K[(size_t)(kv0 + r) * D_MODEL + h * D_K + c4 * 4]);
            float4 kh;
            kh.x = tf32r(kv4.x); kh.y = tf32r(kv4.y); kh.z = tf32r(kv4.z); kh.w = tf32r(kv4.w);
            *reinterpret_cast<float4*>(&Ks[r * KS_STR + c4 * 4]) = kh;
            float4 vv = *reinterpret_cast<const float4*>(
                &V[(size_t)(kv0 + r) * D_MODEL + h * D_K + c4 * 4]);
            float4 vh;
            vh.x = tf32r(vv.x); vh.y = tf32r(vv.y); vh.z = tf32r(vv.z); vh.w = tf32r(vv.w);
            *reinterpret_cast<float4*>(&Vs[r * V_STR + c4 * 4]) = vh;
        }
        __syncthreads();

        if (kv0 <= wrow + 15) {
            float s[8][4];
#pragma unroll
            for (int j = 0; j < 8; j++)
#pragma unroll
                for (int e = 0; e < 4; e++) s[j][e] = 0.f;

#pragma unroll
            for (int kc = 0; kc < 8; kc++) {
#pragma unroll
                for (int j = 0; j < 8; j++) {
                    int rb = (j * 8 + g) * KS_STR + kc * 8 + t4;
                    uint32_t b0 = fau(Ks[rb]);
                    uint32_t b1 = fau(Ks[rb + 4]);
                    mma_tf32(s[j], qh[kc], b0, b1);
                }
            }

            if (kv0 + AK - 1 > wrow) {   // diagonal tile: causal mask
#pragma unroll
                for (int j = 0; j < 8; j++) {
                    int col = kv0 + j * 8 + 2 * t4;
                    int ra = wrow + g, rb2 = wrow + g + 8;
                    if (col > ra)      s[j][0] = -1e30f;
                    if (col + 1 > ra)  s[j][1] = -1e30f;
                    if (col > rb2)     s[j][2] = -1e30f;
                    if (col + 1 > rb2) s[j][3] = -1e30f;
                }
            }

            float mx_a = -1e30f, mx_b = -1e30f;
#pragma unroll
            for (int j = 0; j < 8; j++) {
                mx_a = fmaxf(mx_a, fmaxf(s[j][0], s[j][1]));
                mx_b = fmaxf(mx_b, fmaxf(s[j][2], s[j][3]));
            }
            mx_a = fmaxf(mx_a, __shfl_xor_sync(0xffffffffu, mx_a, 1));
            mx_a = fmaxf(mx_a, __shfl_xor_sync(0xffffffffu, mx_a, 2));
            mx_b = fmaxf(mx_b, __shfl_xor_sync(0xffffffffu, mx_b, 1));
            mx_b = fmaxf(mx_b, __shfl_xor_sync(0xffffffffu, mx_b, 2));
            float nm_a = fmaxf(m_a, mx_a), nm_b = fmaxf(m_b, mx_b);
            float al_a = __expf(m_a - nm_a), al_b = __expf(m_b - nm_b);
            m_a = nm_a; m_b = nm_b;

            float sum_a = 0.f, sum_b = 0.f;
#pragma unroll
            for (int j = 0; j < 8; j++) {
                float p0 = __expf(s[j][0] - m_a);
                float p1 = __expf(s[j][1] - m_a);
                float p2 = __expf(s[j][2] - m_b);
                float p3 = __expf(s[j][3] - m_b);
                sum_a += p0 + p1;
                sum_b += p2 + p3;
                o[j][0] *= al_a; o[j][1] *= al_a;
                o[j][2] *= al_b; o[j][3] *= al_b;
                float2 pa = make_float2(tf32r(p0), tf32r(p1));
                float2 pb = make_float2(tf32r(p2), tf32r(p3));
                *reinterpret_cast<float2*>(&Ps[(w * 16 + g) * PS_STR + j * 8 + 2 * t4]) = pa;
                *reinterpret_cast<float2*>(&Ps[(w * 16 + g + 8) * PS_STR + j * 8 + 2 * t4]) = pb;
            }
            sum_a += __shfl_xor_sync(0xffffffffu, sum_a, 1);
            sum_a += __shfl_xor_sync(0xffffffffu, sum_a, 2);
            sum_b += __shfl_xor_sync(0xffffffffu, sum_b, 1);
            sum_b += __shfl_xor_sync(0xffffffffu, sum_b, 2);
            l_a = l_a * al_a + sum_a;
            l_b = l_b * al_b + sum_b;
            __syncwarp();

#pragma unroll
            for (int kc = 0; kc < 8; kc++) {
                uint32_t pa[4];
                int pr = (w * 16 + g) * PS_STR + kc * 8 + t4;
                pa[0] = fau(Ps[pr]);
                pa[1] = fau(Ps[pr + 8 * PS_STR]);
                pa[2] = fau(Ps[pr + 4]);
                pa[3] = fau(Ps[pr + 8 * PS_STR + 4]);
#pragma unroll
                for (int j = 0; j < 8; j++) {
                    int vb = (kc * 8 + t4) * V_STR + j * 8 + g;
                    uint32_t b0 = fau(Vs[vb]);
                    uint32_t b1 = fau(Vs[vb + 4 * V_STR]);
                    mma_tf32(o[j], pa, b0, b1);
                }
            }
        }
        __syncthreads();
    }

    float ia = 1.0f / l_a, ib = 1.0f / l_b;
#pragma unroll
    for (int j = 0; j < 8; j++) {
        int c = h * D_K + j * 8 + 2 * t4;
        float2 v0 = make_float2(o[j][0] * ia, o[j][1] * ia);
        float2 v1 = make_float2(o[j][2] * ib, o[j][3] * ib);
        *reinterpret_cast<float2*>(&O[(size_t)(wrow + g) * D_MODEL + c]) = v0;
        *reinterpret_cast<float2*>(&O[(size_t)(wrow + g + 8) * D_MODEL + c]) = v1;
    }
}

// ---------------- launcher ----------------
extern "C" void kernel_launch(void* const* d_in, const int* in_sizes, int n_in,
                              void* d_out, int out_size) {
    const float* x  = (const float*)d_in[0];
    const float* Wq = (const float*)d_in[1];
    const float* Wk = (const float*)d_in[2];
    const float* Wv = (const float*)d_in[3];
    const float* Wo = (const float*)d_in[4];
    const int*  pos = (const int*)d_in[5];
    float* out = (float*)d_out;

    float *Qp, *Kp, *Vp, *Ap;
    cudaGetSymbolAddress((void**)&Qp, g_Q);
    cudaGetSymbolAddress((void**)&Kp, g_K);
    cudaGetSymbolAddress((void**)&Vp, g_V);
    cudaGetSymbolAddress((void**)&Ap, g_AT);

    cudaFuncSetAttribute(attn_mma_kernel, cudaFuncAttributeMaxDynamicSharedMemorySize, ATTN_SMEM);

    dim3 ggrid(D_MODEL / GBN, S_LEN / GBM);   // (8, 32)
    gemm3x_kernel<1><<<ggrid, 256>>>(x, Wq, Qp, S_LEN, D_MODEL, D_MODEL, pos);
    gemm3x_kernel<1><<<ggrid, 256>>>(x, Wk, Kp, S_LEN, D_MODEL, D_MODEL, pos);
    gemm3x_kernel<0><<<ggrid, 256>>>(x, Wv, Vp, S_LEN, D_MODEL, D_MODEL, pos);

    dim3 agrid(S_LEN / AQ, NUM_HEADS);        // (32, 16)
    attn_mma_kernel<<<agrid, 256, ATTN_SMEM>>>(Qp, Kp, Vp, Ap);

    gemm3x_kernel<0><<<ggrid, 256>>>(Ap, Wo, out, S_LEN, D_MODEL, D_MODEL, pos);
}

// round 7
// speedup vs baseline: 1.7990x; 1.3015x over previous
#include <cuda_runtime.h>
#include <math.h>
#include <stdint.h>

#define S_LEN 4096
#define D_MODEL 1024
#define NUM_HEADS 16
#define D_K 64

// ---------------- scratch (no allocs allowed) ----------------
__device__ float g_Q[S_LEN * D_MODEL];
__device__ float g_K[S_LEN * D_MODEL];
__device__ float g_V[S_LEN * D_MODEL];
__device__ float g_AT[S_LEN * D_MODEL];

// ---------------- helpers ----------------
__device__ __forceinline__ float tf32r(float x) {
    uint32_t u;
    asm("cvt.rna.tf32.f32 %0, %1;" : "=r"(u) : "f"(x));
    return __uint_as_float(u);
}
__device__ __forceinline__ uint32_t fau(float x) { return __float_as_uint(x); }

__device__ __forceinline__ void mma_tf32(float* d, const uint32_t* a, uint32_t b0, uint32_t b1) {
    asm volatile(
        "mma.sync.aligned.m16n8k8.row.col.f32.tf32.tf32.f32 "
        "{%0,%1,%2,%3}, {%4,%5,%6,%7}, {%8,%9}, {%0,%1,%2,%3};"
        : "+f"(d[0]), "+f"(d[1]), "+f"(d[2]), "+f"(d[3])
        : "r"(a[0]), "r"(a[1]), "r"(a[2]), "r"(a[3]), "r"(b0), "r"(b1));
}

// ---------------- 2xTF32 GEMM: C[m,n] = sum_k A[m,k]*B[n,k] ----------------
// A split hi/lo (activations compensated), B rounded to tf32 (weights).
#define GBM 128
#define GBN 128
#define GBK 16
#define G_STR 20

template<int ROPE>
__global__ __launch_bounds__(256)
void gemm2x_kernel(const float* __restrict__ A, const float* __restrict__ B,
                   float* __restrict__ C, int M, int N, int K,
                   const int* __restrict__ pos) {
    __shared__ float Ash[GBM * G_STR];
    __shared__ float Asl[GBM * G_STR];
    __shared__ float Bsh[GBN * G_STR];

    const int tid = threadIdx.x;
    const int m0 = blockIdx.y * GBM;
    const int n0 = blockIdx.x * GBN;
    const int w = tid >> 5, lane = tid & 31;
    const int g = lane >> 2, t4 = lane & 3;
    const int wm = w >> 1, wn = w & 1;     // 4x2 warp grid, warp tile 32x64

    float acc[2][8][4];
#pragma unroll
    for (int i = 0; i < 2; i++)
#pragma unroll
        for (int j = 0; j < 8; j++)
#pragma unroll
            for (int e = 0; e < 4; e++) acc[i][j][e] = 0.f;

    for (int k0 = 0; k0 < K; k0 += GBK) {
#pragma unroll
        for (int it = 0; it < 2; it++) {
            int idx = tid + it * 256;        // float4 index: 512 per tile
            int row = idx >> 2;
            int c4  = idx & 3;
            float4 va = *reinterpret_cast<const float4*>(&A[(size_t)(m0 + row) * K + k0 + c4 * 4]);
            float4 hi, lo;
            hi.x = tf32r(va.x); lo.x = tf32r(va.x - hi.x);
            hi.y = tf32r(va.y); lo.y = tf32r(va.y - hi.y);
            hi.z = tf32r(va.z); lo.z = tf32r(va.z - hi.z);
            hi.w = tf32r(va.w); lo.w = tf32r(va.w - hi.w);
            *reinterpret_cast<float4*>(&Ash[row * G_STR + c4 * 4]) = hi;
            *reinterpret_cast<float4*>(&Asl[row * G_STR + c4 * 4]) = lo;
            float4 vb = *reinterpret_cast<const float4*>(&B[(size_t)(n0 + row) * K + k0 + c4 * 4]);
            float4 bh;
            bh.x = tf32r(vb.x); bh.y = tf32r(vb.y); bh.z = tf32r(vb.z); bh.w = tf32r(vb.w);
            *reinterpret_cast<float4*>(&Bsh[row * G_STR + c4 * 4]) = bh;
        }
        __syncthreads();

#pragma unroll
        for (int kk = 0; kk < GBK; kk += 8) {
            uint32_t ah[2][4], al[2][4];
#pragma unroll
            for (int i = 0; i < 2; i++) {
                int r = (wm * 32 + i * 16 + g) * G_STR + kk + t4;
                ah[i][0] = fau(Ash[r]);
                ah[i][1] = fau(Ash[r + 8 * G_STR]);
                ah[i][2] = fau(Ash[r + 4]);
                ah[i][3] = fau(Ash[r + 8 * G_STR + 4]);
                al[i][0] = fau(Asl[r]);
                al[i][1] = fau(Asl[r + 8 * G_STR]);
                al[i][2] = fau(Asl[r + 4]);
                al[i][3] = fau(Asl[r + 8 * G_STR + 4]);
            }
#pragma unroll
            for (int j = 0; j < 8; j++) {
                int rb = (wn * 64 + j * 8 + g) * G_STR + kk + t4;
                uint32_t bh0 = fau(Bsh[rb]);
                uint32_t bh1 = fau(Bsh[rb + 4]);
#pragma unroll
                for (int i = 0; i < 2; i++) {
                    mma_tf32(acc[i][j], ah[i], bh0, bh1);
                    mma_tf32(acc[i][j], al[i], bh0, bh1);
                }
            }
        }
        __syncthreads();
    }

    // epilogue; ROPE is compile-time
    float invf[8];
    if (ROPE) {
#pragma unroll
        for (int j = 0; j < 8; j++) {
            int p = ((wn * 64 + j * 8 + 2 * t4) & 63) >> 1;
            invf[j] = powf(10000.0f, -(float)(2 * p) / (float)D_K);
        }
    }
#pragma unroll
    for (int i = 0; i < 2; i++) {
        int r1 = m0 + wm * 32 + i * 16 + g;
        int r2 = r1 + 8;
        float p1 = 0.f, p2 = 0.f;
        if (ROPE) { p1 = (float)pos[r1]; p2 = (float)pos[r2]; }
#pragma unroll
        for (int j = 0; j < 8; j++) {
            int c = n0 + wn * 64 + j * 8 + 2 * t4;
            float v0 = acc[i][j][0], v1 = acc[i][j][1];
            float v2 = acc[i][j][2], v3 = acc[i][j][3];
            if (ROPE) {
                float s, cs;
                sincosf(p1 * invf[j], &s, &cs);
                float u0 = v0 * cs - v1 * s, u1 = v0 * s + v1 * cs;
                v0 = u0; v1 = u1;
                sincosf(p2 * invf[j], &s, &cs);
                float u2 = v2 * cs - v3 * s, u3 = v2 * s + v3 * cs;
                v2 = u2; v3 = u3;
            }
            *reinterpret_cast<float2*>(&C[(size_t)r1 * N + c]) = make_float2(v0, v1);
            *reinterpret_cast<float2*>(&C[(size_t)r2 * N + c]) = make_float2(v2, v3);
        }
    }
}

// ============ Flash attention, tf32 mma, 2 CTAs/SM (R6-proven) ============
#define AQ 128
#define AK 64
#define KS_STR 68
#define V_STR  72
#define PS_STR 68
#define ATTN_SMEM ((AK * KS_STR + AK * V_STR + AQ * PS_STR) * 4)

__global__ __launch_bounds__(256, 2)
void attn_mma_kernel(const float* __restrict__ Q, const float* __restrict__ K,
                     const float* __restrict__ V, float* __restrict__ O) {
    extern __shared__ float sm[];
    float* Ks = sm;                      // [64][68] tf32
    float* Vs = Ks + AK * KS_STR;        // [64][72] tf32
    float* Ps = Vs + AK * V_STR;         // [128][68] tf32

    const int h   = blockIdx.y;
    const int q0  = (gridDim.x - 1 - blockIdx.x) * AQ;  // big CTAs first
    const int tid = threadIdx.x;
    const int w = tid >> 5, lane = tid & 31;
    const int g = lane >> 2, t4 = lane & 3;
    const int wrow = q0 + w * 16;

    // Q fragments (tf32), scaled by 1/sqrt(dk)
    uint32_t qh[8][4];
    {
        const float* qb = Q + (size_t)wrow * D_MODEL + h * D_K;
#pragma unroll
        for (int kc = 0; kc < 8; kc++) {
            int c0 = kc * 8 + t4;
            qh[kc][0] = fau(tf32r(qb[(size_t)g * D_MODEL + c0] * 0.125f));
            qh[kc][1] = fau(tf32r(qb[(size_t)(g + 8) * D_MODEL + c0] * 0.125f));
            qh[kc][2] = fau(tf32r(qb[(size_t)g * D_MODEL + c0 + 4] * 0.125f));
            qh[kc][3] = fau(tf32r(qb[(size_t)(g + 8) * D_MODEL + c0 + 4] * 0.125f));
        }
    }

    float o[8][4];
#pragma unroll
    for (int j = 0; j < 8; j++)
#pragma unroll
        for (int e = 0; e < 4; e++) o[j][e] = 0.f;
    float m_a = -1e30f, m_b = -1e30f, l_a = 0.f, l_b = 0.f;

    for (int kv0 = 0; kv0 < q0 + AQ; kv0 += AK) {
#pragma unroll
        for (int it = 0; it < 4; it++) {
            int idx = tid + it * 256;
            int r = idx >> 4, c4 = idx & 15;
            float4 kv4 = *reinterpret_cast<const float4*>(
                &K[(size_t)(kv0 + r) * D_MODEL + h * D_K + c4 * 4]);
            float4 kh;
            kh.x = tf32r(kv4.x); kh.y = tf32r(kv4.y); kh.z = tf32r(kv4.z); kh.w = tf32r(kv4.w);
            *reinterpret_cast<float4*>(&Ks[r * KS_STR + c4 * 4]) = kh;
            float4 vv = *reinterpret_cast<const float4*>(
                &V[(size_t)(kv0 + r) * D_MODEL + h * D_K + c4 * 4]);
            float4 vh;
            vh.x = tf32r(vv.x); vh.y = tf32r(vv.y); vh.z = tf32r(vv.z); vh.w = tf32r(vv.w);
            *reinterpret_cast<float4*>(&Vs[r * V_STR + c4 * 4]) = vh;
        }
        __syncthreads();

        if (kv0 <= wrow + 15) {
            float s[8][4];
#pragma unroll
            for (int j = 0; j < 8; j++)
#pragma unroll
                for (int e = 0; e < 4; e++) s[j][e] = 0.f;

#pragma unroll
            for (int kc = 0; kc < 8; kc++) {
#pragma unroll
                for (int j = 0; j < 8; j++) {
                    int rb = (j * 8 + g) * KS_STR + kc * 8 + t4;
                    uint32_t b0 = fau(Ks[rb]);
                    uint32_t b1 = fau(Ks[rb + 4]);
                    mma_tf32(s[j], qh[kc], b0, b1);
                }
            }

            if (kv0 + AK - 1 > wrow) {   // diagonal tile: causal mask
#pragma unroll
                for (int j = 0; j < 8; j++) {
                    int col = kv0 + j * 8 + 2 * t4;
                    int ra = wrow + g, rb2 = wrow + g + 8;
                    if (col > ra)      s[j][0] = -1e30f;
                    if (col + 1 > ra)  s[j][1] = -1e30f;
                    if (col > rb2)     s[j][2] = -1e30f;
                    if (col + 1 > rb2) s[j][3] = -1e30f;
                }
            }

            float mx_a = -1e30f, mx_b = -1e30f;
#pragma unroll
            for (int j = 0; j < 8; j++) {
                mx_a = fmaxf(mx_a, fmaxf(s[j][0], s[j][1]));
                mx_b = fmaxf(mx_b, fmaxf(s[j][2], s[j][3]));
            }
            mx_a = fmaxf(mx_a, __shfl_xor_sync(0xffffffffu, mx_a, 1));
            mx_a = fmaxf(mx_a, __shfl_xor_sync(0xffffffffu, mx_a, 2));
            mx_b = fmaxf(mx_b, __shfl_xor_sync(0xffffffffu, mx_b, 1));
            mx_b = fmaxf(mx_b, __shfl_xor_sync(0xffffffffu, mx_b, 2));
            float nm_a = fmaxf(m_a, mx_a), nm_b = fmaxf(m_b, mx_b);
            float al_a = __expf(m_a - nm_a), al_b = __expf(m_b - nm_b);
            m_a = nm_a; m_b = nm_b;

            float sum_a = 0.f, sum_b = 0.f;
#pragma unroll
            for (int j = 0; j < 8; j++) {
                float p0 = __expf(s[j][0] - m_a);
                float p1 = __expf(s[j][1] - m_a);
                float p2 = __expf(s[j][2] - m_b);
                float p3 = __expf(s[j][3] - m_b);
                sum_a += p0 + p1;
                sum_b += p2 + p3;
                o[j][0] *= al_a; o[j][1] *= al_a;
                o[j][2] *= al_b; o[j][3] *= al_b;
                float2 pa = make_float2(tf32r(p0), tf32r(p1));
                float2 pb = make_float2(tf32r(p2), tf32r(p3));
                *reinterpret_cast<float2*>(&Ps[(w * 16 + g) * PS_STR + j * 8 + 2 * t4]) = pa;
                *reinterpret_cast<float2*>(&Ps[(w * 16 + g + 8) * PS_STR + j * 8 + 2 * t4]) = pb;
            }
            sum_a += __shfl_xor_sync(0xffffffffu, sum_a, 1);
            sum_a += __shfl_xor_sync(0xffffffffu, sum_a, 2);
            sum_b += __shfl_xor_sync(0xffffffffu, sum_b, 1);
            sum_b += __shfl_xor_sync(0xffffffffu, sum_b, 2);
            l_a = l_a * al_a + sum_a;
            l_b = l_b * al_b + sum_b;
            __syncwarp();

#pragma unroll
            for (int kc = 0; kc < 8; kc++) {
                uint32_t pa[4];
                int pr = (w * 16 + g) * PS_STR + kc * 8 + t4;
                pa[0] = fau(Ps[pr]);
                pa[1] = fau(Ps[pr + 8 * PS_STR]);
                pa[2] = fau(Ps[pr + 4]);
                pa[3] = fau(Ps[pr + 8 * PS_STR + 4]);
#pragma unroll
                for (int j = 0; j < 8; j++) {
                    int vb = (kc * 8 + t4) * V_STR + j * 8 + g;
                    uint32_t b0 = fau(Vs[vb]);
                    uint32_t b1 = fau(Vs[vb + 4 * V_STR]);
                    mma_tf32(o[j], pa, b0, b1);
                }
            }
        }
        __syncthreads();
    }

    float ia = 1.0f / l_a, ib = 1.0f / l_b;
#pragma unroll
    for (int j = 0; j < 8; j++) {
        int c = h * D_K + j * 8 + 2 * t4;
        float2 v0 = make_float2(o[j][0] * ia, o[j][1] * ia);
        float2 v1 = make_float2(o[j][2] * ib, o[j][3] * ib);
        *reinterpret_cast<float2*>(&O[(size_t)(wrow + g) * D_MODEL + c]) = v0;
        *reinterpret_cast<float2*>(&O[(size_t)(wrow + g + 8) * D_MODEL + c]) = v1;
    }
}

// ---------------- launcher ----------------
extern "C" void kernel_launch(void* const* d_in, const int* in_sizes, int n_in,
                              void* d_out, int out_size) {
    const float* x  = (const float*)d_in[0];
    const float* Wq = (const float*)d_in[1];
    const float* Wk = (const float*)d_in[2];
    const float* Wv = (const float*)d_in[3];
    const float* Wo = (const float*)d_in[4];
    const int*  pos = (const int*)d_in[5];
    float* out = (float*)d_out;

    float *Qp, *Kp, *Vp, *Ap;
    cudaGetSymbolAddress((void**)&Qp, g_Q);
    cudaGetSymbolAddress((void**)&Kp, g_K);
    cudaGetSymbolAddress((void**)&Vp, g_V);
    cudaGetSymbolAddress((void**)&Ap, g_AT);

    cudaFuncSetAttribute(attn_mma_kernel, cudaFuncAttributeMaxDynamicSharedMemorySize, ATTN_SMEM);

    dim3 ggrid(D_MODEL / GBN, S_LEN / GBM);   // (8, 32)
    gemm2x_kernel<1><<<ggrid, 256>>>(x, Wq, Qp, S_LEN, D_MODEL, D_MODEL, pos);
    gemm2x_kernel<1><<<ggrid, 256>>>(x, Wk, Kp, S_LEN, D_MODEL, D_MODEL, pos);
    gemm2x_kernel<0><<<ggrid, 256>>>(x, Wv, Vp, S_LEN, D_MODEL, D_MODEL, pos);

    dim3 agrid(S_LEN / AQ, NUM_HEADS);        // (32, 16)
    attn_mma_kernel<<<agrid, 256, ATTN_SMEM>>>(Qp, Kp, Vp, Ap);

    gemm2x_kernel<0><<<ggrid, 256>>>(Ap, Wo, out, S_LEN, D_MODEL, D_MODEL, pos);
}

// round 8
// speedup vs baseline: 1.8500x; 1.0283x over previous
#include <cuda_runtime.h>
#include <math.h>
#include <stdint.h>

#define S_LEN 4096
#define D_MODEL 1024
#define NUM_HEADS 16
#define D_K 64

// ---------------- scratch (no allocs allowed) ----------------
__device__ float g_Q[S_LEN * D_MODEL];
__device__ float g_K[S_LEN * D_MODEL];
__device__ float g_V[S_LEN * D_MODEL];
__device__ float g_AT[S_LEN * D_MODEL];

// ---------------- helpers ----------------
__device__ __forceinline__ float tf32r(float x) {
    uint32_t u;
    asm("cvt.rna.tf32.f32 %0, %1;" : "=r"(u) : "f"(x));
    return __uint_as_float(u);
}
__device__ __forceinline__ uint32_t fau(float x) { return __float_as_uint(x); }

__device__ __forceinline__ void mma_tf32(float* d, const uint32_t* a, uint32_t b0, uint32_t b1) {
    asm volatile(
        "mma.sync.aligned.m16n8k8.row.col.f32.tf32.tf32.f32 "
        "{%0,%1,%2,%3}, {%4,%5,%6,%7}, {%8,%9}, {%0,%1,%2,%3};"
        : "+f"(d[0]), "+f"(d[1]), "+f"(d[2]), "+f"(d[3])
        : "r"(a[0]), "r"(a[1]), "r"(a[2]), "r"(a[3]), "r"(b0), "r"(b1));
}

__device__ __forceinline__ void cp_async16(uint32_t smem_addr, const void* gptr) {
    asm volatile("cp.async.cg.shared.global [%0], [%1], 16;\n"
                 :: "r"(smem_addr), "l"(gptr));
}
__device__ __forceinline__ void cp_commit() {
    asm volatile("cp.async.commit_group;\n" ::: "memory");
}
template<int N>
__device__ __forceinline__ void cp_wait() {
    asm volatile("cp.async.wait_group %0;\n" :: "n"(N) : "memory");
}

// ---------------- 2xTF32 GEMM: C[m,n] = sum_k A[m,k]*B[n,k] ----------------
// A split hi/lo (activations compensated), B rounded to tf32 (weights).
#define GBM 128
#define GBN 128
#define GBK 16
#define G_STR 20

template<int ROPE, int TFOUT>
__global__ __launch_bounds__(256)
void gemm2x_kernel(const float* __restrict__ A, const float* __restrict__ B,
                   float* __restrict__ C, int M, int N, int K,
                   const int* __restrict__ pos) {
    __shared__ float Ash[GBM * G_STR];
    __shared__ float Asl[GBM * G_STR];
    __shared__ float Bsh[GBN * G_STR];

    const int tid = threadIdx.x;
    const int m0 = blockIdx.y * GBM;
    const int n0 = blockIdx.x * GBN;
    const int w = tid >> 5, lane = tid & 31;
    const int g = lane >> 2, t4 = lane & 3;
    const int wm = w >> 1, wn = w & 1;     // 4x2 warp grid, warp tile 32x64

    float acc[2][8][4];
#pragma unroll
    for (int i = 0; i < 2; i++)
#pragma unroll
        for (int j = 0; j < 8; j++)
#pragma unroll
            for (int e = 0; e < 4; e++) acc[i][j][e] = 0.f;

    for (int k0 = 0; k0 < K; k0 += GBK) {
#pragma unroll
        for (int it = 0; it < 2; it++) {
            int idx = tid + it * 256;        // float4 index: 512 per tile
            int row = idx >> 2;
            int c4  = idx & 3;
            float4 va = *reinterpret_cast<const float4*>(&A[(size_t)(m0 + row) * K + k0 + c4 * 4]);
            float4 hi, lo;
            hi.x = tf32r(va.x); lo.x = tf32r(va.x - hi.x);
            hi.y = tf32r(va.y); lo.y = tf32r(va.y - hi.y);
            hi.z = tf32r(va.z); lo.z = tf32r(va.z - hi.z);
            hi.w = tf32r(va.w); lo.w = tf32r(va.w - hi.w);
            *reinterpret_cast<float4*>(&Ash[row * G_STR + c4 * 4]) = hi;
            *reinterpret_cast<float4*>(&Asl[row * G_STR + c4 * 4]) = lo;
            float4 vb = *reinterpret_cast<const float4*>(&B[(size_t)(n0 + row) * K + k0 + c4 * 4]);
            float4 bh;
            bh.x = tf32r(vb.x); bh.y = tf32r(vb.y); bh.z = tf32r(vb.z); bh.w = tf32r(vb.w);
            *reinterpret_cast<float4*>(&Bsh[row * G_STR + c4 * 4]) = bh;
        }
        __syncthreads();

#pragma unroll
        for (int kk = 0; kk < GBK; kk += 8) {
            uint32_t ah[2][4], al[2][4];
#pragma unroll
            for (int i = 0; i < 2; i++) {
                int r = (wm * 32 + i * 16 + g) * G_STR + kk + t4;
                ah[i][0] = fau(Ash[r]);
                ah[i][1] = fau(Ash[r + 8 * G_STR]);
                ah[i][2] = fau(Ash[r + 4]);
                ah[i][3] = fau(Ash[r + 8 * G_STR + 4]);
                al[i][0] = fau(Asl[r]);
                al[i][1] = fau(Asl[r + 8 * G_STR]);
                al[i][2] = fau(Asl[r + 4]);
                al[i][3] = fau(Asl[r + 8 * G_STR + 4]);
            }
#pragma unroll
            for (int j = 0; j < 8; j++) {
                int rb = (wn * 64 + j * 8 + g) * G_STR + kk + t4;
                uint32_t bh0 = fau(Bsh[rb]);
                uint32_t bh1 = fau(Bsh[rb + 4]);
#pragma unroll
                for (int i = 0; i < 2; i++) {
                    mma_tf32(acc[i][j], ah[i], bh0, bh1);
                    mma_tf32(acc[i][j], al[i], bh0, bh1);
                }
            }
        }
        __syncthreads();
    }

    // epilogue; ROPE / TFOUT compile-time
    float invf[8];
    if (ROPE) {
#pragma unroll
        for (int j = 0; j < 8; j++) {
            int p = ((wn * 64 + j * 8 + 2 * t4) & 63) >> 1;
            invf[j] = powf(10000.0f, -(float)(2 * p) / (float)D_K);
        }
    }
#pragma unroll
    for (int i = 0; i < 2; i++) {
        int r1 = m0 + wm * 32 + i * 16 + g;
        int r2 = r1 + 8;
        float p1 = 0.f, p2 = 0.f;
        if (ROPE) { p1 = (float)pos[r1]; p2 = (float)pos[r2]; }
#pragma unroll
        for (int j = 0; j < 8; j++) {
            int c = n0 + wn * 64 + j * 8 + 2 * t4;
            float v0 = acc[i][j][0], v1 = acc[i][j][1];
            float v2 = acc[i][j][2], v3 = acc[i][j][3];
            if (ROPE) {
                float s, cs;
                sincosf(p1 * invf[j], &s, &cs);
                float u0 = v0 * cs - v1 * s, u1 = v0 * s + v1 * cs;
                v0 = u0; v1 = u1;
                sincosf(p2 * invf[j], &s, &cs);
                float u2 = v2 * cs - v3 * s, u3 = v2 * s + v3 * cs;
                v2 = u2; v3 = u3;
            }
            if (TFOUT) {
                v0 = tf32r(v0); v1 = tf32r(v1); v2 = tf32r(v2); v3 = tf32r(v3);
            }
            *reinterpret_cast<float2*>(&C[(size_t)r1 * N + c]) = make_float2(v0, v1);
            *reinterpret_cast<float2*>(&C[(size_t)r2 * N + c]) = make_float2(v2, v3);
        }
    }
}

// ============ Flash attention, tf32 mma, cp.async double-buffered K/V ============
// K/V in gmem are already tf32-rounded (done in GEMM epilogue) -> raw async copy.
#define AQ 128
#define AK 64
#define KS_STR 68
#define V_STR  72
#define PS_STR 68
#define K_STAGE (AK * KS_STR)
#define V_STAGE (AK * V_STR)
// layout: K0 K1 V0 V1 Ps
#define ATTN_SMEM ((2 * K_STAGE + 2 * V_STAGE + AQ * PS_STR) * 4)

__global__ __launch_bounds__(256, 2)
void attn_mma_kernel(const float* __restrict__ Q, const float* __restrict__ K,
                     const float* __restrict__ V, float* __restrict__ O) {
    extern __shared__ float sm[];
    float* Kb = sm;                        // 2 stages [64][68]
    float* Vb = sm + 2 * K_STAGE;          // 2 stages [64][72]
    float* Ps = sm + 2 * K_STAGE + 2 * V_STAGE;  // [128][68]

    const int h   = blockIdx.y;
    const int q0  = (gridDim.x - 1 - blockIdx.x) * AQ;  // big CTAs first
    const int tid = threadIdx.x;
    const int w = tid >> 5, lane = tid & 31;
    const int g = lane >> 2, t4 = lane & 3;
    const int wrow = q0 + w * 16;

    const uint32_t smem_base = (uint32_t)__cvta_generic_to_shared(sm);
    const int lr  = tid >> 4;          // 0..15: row pair base for cp.async (16 float4/row)
    const int lc4 = tid & 15;

    // Q fragments (tf32), scaled by 1/sqrt(dk)
    uint32_t qh[8][4];
    {
        const float* qb = Q + (size_t)wrow * D_MODEL + h * D_K;
#pragma unroll
        for (int kc = 0; kc < 8; kc++) {
            int c0 = kc * 8 + t4;
            qh[kc][0] = fau(tf32r(qb[(size_t)g * D_MODEL + c0] * 0.125f));
            qh[kc][1] = fau(tf32r(qb[(size_t)(g + 8) * D_MODEL + c0] * 0.125f));
            qh[kc][2] = fau(tf32r(qb[(size_t)g * D_MODEL + c0 + 4] * 0.125f));
            qh[kc][3] = fau(tf32r(qb[(size_t)(g + 8) * D_MODEL + c0 + 4] * 0.125f));
        }
    }

    float o[8][4];
#pragma unroll
    for (int j = 0; j < 8; j++)
#pragma unroll
        for (int e = 0; e < 4; e++) o[j][e] = 0.f;
    float m_a = -1e30f, m_b = -1e30f, l_a = 0.f, l_b = 0.f;

    const int nt = (q0 + AQ) / AK;   // number of kv tiles

    // issue cp.async for tile t into stage t&1
    auto issue_tile = [&](int t) {
        int kv0 = t * AK;
        int st  = t & 1;
        uint32_t kdst = smem_base + (st * K_STAGE) * 4;
        uint32_t vdst = smem_base + (2 * K_STAGE + st * V_STAGE) * 4;
#pragma unroll
        for (int it = 0; it < 4; it++) {
            int r  = lr + it * 16;
            const float* kg = &K[(size_t)(kv0 + r) * D_MODEL + h * D_K + lc4 * 4];
            const float* vg = &V[(size_t)(kv0 + r) * D_MODEL + h * D_K + lc4 * 4];
            cp_async16(kdst + (r * KS_STR + lc4 * 4) * 4, kg);
            cp_async16(vdst + (r * V_STR + lc4 * 4) * 4, vg);
        }
        cp_commit();
    };

    issue_tile(0);

    for (int t = 0; t < nt; t++) {
        if (t + 1 < nt) {
            issue_tile(t + 1);
            cp_wait<1>();
        } else {
            cp_wait<0>();
        }
        __syncthreads();

        const int kv0 = t * AK;
        const float* Ks = Kb + (t & 1) * K_STAGE;
        const float* Vs = Vb + (t & 1) * V_STAGE;

        if (kv0 <= wrow + 15) {
            float s[8][4];
#pragma unroll
            for (int j = 0; j < 8; j++)
#pragma unroll
                for (int e = 0; e < 4; e++) s[j][e] = 0.f;

#pragma unroll
            for (int kc = 0; kc < 8; kc++) {
#pragma unroll
                for (int j = 0; j < 8; j++) {
                    int rb = (j * 8 + g) * KS_STR + kc * 8 + t4;
                    uint32_t b0 = fau(Ks[rb]);
                    uint32_t b1 = fau(Ks[rb + 4]);
                    mma_tf32(s[j], qh[kc], b0, b1);
                }
            }

            if (kv0 + AK - 1 > wrow) {   // diagonal tile: causal mask
#pragma unroll
                for (int j = 0; j < 8; j++) {
                    int col = kv0 + j * 8 + 2 * t4;
                    int ra = wrow + g, rb2 = wrow + g + 8;
                    if (col > ra)      s[j][0] = -1e30f;
                    if (col + 1 > ra)  s[j][1] = -1e30f;
                    if (col > rb2)     s[j][2] = -1e30f;
                    if (col + 1 > rb2) s[j][3] = -1e30f;
                }
            }

            float mx_a = -1e30f, mx_b = -1e30f;
#pragma unroll
            for (int j = 0; j < 8; j++) {
                mx_a = fmaxf(mx_a, fmaxf(s[j][0], s[j][1]));
                mx_b = fmaxf(mx_b, fmaxf(s[j][2], s[j][3]));
            }
            mx_a = fmaxf(mx_a, __shfl_xor_sync(0xffffffffu, mx_a, 1));
            mx_a = fmaxf(mx_a, __shfl_xor_sync(0xffffffffu, mx_a, 2));
            mx_b = fmaxf(mx_b, __shfl_xor_sync(0xffffffffu, mx_b, 1));
            mx_b = fmaxf(mx_b, __shfl_xor_sync(0xffffffffu, mx_b, 2));
            float nm_a = fmaxf(m_a, mx_a), nm_b = fmaxf(m_b, mx_b);
            float al_a = __expf(m_a - nm_a), al_b = __expf(m_b - nm_b);
            m_a = nm_a; m_b = nm_b;

            float sum_a = 0.f, sum_b = 0.f;
#pragma unroll
            for (int j = 0; j < 8; j++) {
                float p0 = __expf(s[j][0] - m_a);
                float p1 = __expf(s[j][1] - m_a);
                float p2 = __expf(s[j][2] - m_b);
                float p3 = __expf(s[j][3] - m_b);
                sum_a += p0 + p1;
                sum_b += p2 + p3;
                o[j][0] *= al_a; o[j][1] *= al_a;
                o[j][2] *= al_b; o[j][3] *= al_b;
                float2 pa = make_float2(tf32r(p0), tf32r(p1));
                float2 pb = make_float2(tf32r(p2), tf32r(p3));
                *reinterpret_cast<float2*>(&Ps[(w * 16 + g) * PS_STR + j * 8 + 2 * t4]) = pa;
                *reinterpret_cast<float2*>(&Ps[(w * 16 + g + 8) * PS_STR + j * 8 + 2 * t4]) = pb;
            }
            sum_a += __shfl_xor_sync(0xffffffffu, sum_a, 1);
            sum_a += __shfl_xor_sync(0xffffffffu, sum_a, 2);
            sum_b += __shfl_xor_sync(0xffffffffu, sum_b, 1);
            sum_b += __shfl_xor_sync(0xffffffffu, sum_b, 2);
            l_a = l_a * al_a + sum_a;
            l_b = l_b * al_b + sum_b;
            __syncwarp();

#pragma unroll
            for (int kc = 0; kc < 8; kc++) {
                uint32_t pa[4];
                int pr = (w * 16 + g) * PS_STR + kc * 8 + t4;
                pa[0] = fau(Ps[pr]);
                pa[1] = fau(Ps[pr + 8 * PS_STR]);
                pa[2] = fau(Ps[pr + 4]);
                pa[3] = fau(Ps[pr + 8 * PS_STR + 4]);
#pragma unroll
                for (int j = 0; j < 8; j++) {
                    int vb = (kc * 8 + t4) * V_STR + j * 8 + g;
                    uint32_t b0 = fau(Vs[vb]);
                    uint32_t b1 = fau(Vs[vb + 4 * V_STR]);
                    mma_tf32(o[j], pa, b0, b1);
                }
            }
        }
        __syncthreads();
    }

    float ia = 1.0f / l_a, ib = 1.0f / l_b;
#pragma unroll
    for (int j = 0; j < 8; j++) {
        int c = h * D_K + j * 8 + 2 * t4;
        float2 v0 = make_float2(o[j][0] * ia, o[j][1] * ia);
        float2 v1 = make_float2(o[j][2] * ib, o[j][3] * ib);
        *reinterpret_cast<float2*>(&O[(size_t)(wrow + g) * D_MODEL + c]) = v0;
        *reinterpret_cast<float2*>(&O[(size_t)(wrow + g + 8) * D_MODEL + c]) = v1;
    }
}

// ---------------- launcher ----------------
extern "C" void kernel_launch(void* const* d_in, const int* in_sizes, int n_in,
                              void* d_out, int out_size) {
    const float* x  = (const float*)d_in[0];
    const float* Wq = (const float*)d_in[1];
    const float* Wk = (const float*)d_in[2];
    const float* Wv = (const float*)d_in[3];
    const float* Wo = (const float*)d_in[4];
    const int*  pos = (const int*)d_in[5];
    float* out = (float*)d_out;

    float *Qp, *Kp, *Vp, *Ap;
    cudaGetSymbolAddress((void**)&Qp, g_Q);
    cudaGetSymbolAddress((void**)&Kp, g_K);
    cudaGetSymbolAddress((void**)&Vp, g_V);
    cudaGetSymbolAddress((void**)&Ap, g_AT);

    cudaFuncSetAttribute(attn_mma_kernel, cudaFuncAttributeMaxDynamicSharedMemorySize, ATTN_SMEM);

    dim3 ggrid(D_MODEL / GBN, S_LEN / GBM);   // (8, 32)
    gemm2x_kernel<1,0><<<ggrid, 256>>>(x, Wq, Qp, S_LEN, D_MODEL, D_MODEL, pos);
    gemm2x_kernel<1,1><<<ggrid, 256>>>(x, Wk, Kp, S_LEN, D_MODEL, D_MODEL, pos);
    gemm2x_kernel<0,1><<<ggrid, 256>>>(x, Wv, Vp, S_LEN, D_MODEL, D_MODEL, pos);

    dim3 agrid(S_LEN / AQ, NUM_HEADS);        // (32, 16)
    attn_mma_kernel<<<agrid, 256, ATTN_SMEM>>>(Qp, Kp, Vp, Ap);

    gemm2x_kernel<0,0><<<ggrid, 256>>>(Ap, Wo, out, S_LEN, D_MODEL, D_MODEL, pos);
}

// round 12
// speedup vs baseline: 1.9609x; 1.0600x over previous
#include <cuda_runtime.h>
#include <math.h>
#include <stdint.h>

#define S_LEN 4096
#define D_MODEL 1024
#define NUM_HEADS 16
#define D_K 64

// ---------------- scratch (no allocs allowed) ----------------
__device__ float g_Q[S_LEN * D_MODEL];
__device__ float g_K[S_LEN * D_MODEL];
__device__ float g_V[S_LEN * D_MODEL];
__device__ float g_AT[S_LEN * D_MODEL];
__device__ float g_XH[S_LEN * D_MODEL];   // hi plane of activations
__device__ float g_XL[S_LEN * D_MODEL];   // lo plane of activations
__device__ float g_W [D_MODEL * D_MODEL]; // tf32-rounded weight (serially reused)

// ---------------- helpers ----------------
__device__ __forceinline__ float tf32r(float x) {
    uint32_t u;
    asm("cvt.rna.tf32.f32 %0, %1;" : "=r"(u) : "f"(x));
    return __uint_as_float(u);
}
__device__ __forceinline__ uint32_t fau(float x) { return __float_as_uint(x); }

__device__ __forceinline__ void mma_tf32(float* d, const uint32_t* a, uint32_t b0, uint32_t b1) {
    asm volatile(
        "mma.sync.aligned.m16n8k8.row.col.f32.tf32.tf32.f32 "
        "{%0,%1,%2,%3}, {%4,%5,%6,%7}, {%8,%9}, {%0,%1,%2,%3};"
        : "+f"(d[0]), "+f"(d[1]), "+f"(d[2]), "+f"(d[3])
        : "r"(a[0]), "r"(a[1]), "r"(a[2]), "r"(a[3]), "r"(b0), "r"(b1));
}

__device__ __forceinline__ void cp_async16(uint32_t smem_addr, const void* gptr) {
    asm volatile("cp.async.cg.shared.global [%0], [%1], 16;\n"
                 :: "r"(smem_addr), "l"(gptr));
}
__device__ __forceinline__ void cp_commit() {
    asm volatile("cp.async.commit_group;\n" ::: "memory");
}
template<int N>
__device__ __forceinline__ void cp_wait() {
    asm volatile("cp.async.wait_group %0;\n" :: "n"(N) : "memory");
}

// ---------------- prepasses ----------------
__global__ void split_kernel(const float4* __restrict__ src, float4* __restrict__ hi,
                             float4* __restrict__ lo, int n4) {
    int i = blockIdx.x * blockDim.x + threadIdx.x;
    if (i >= n4) return;
    float4 v = src[i];
    float4 h, l;
    h.x = tf32r(v.x); l.x = tf32r(v.x - h.x);
    h.y = tf32r(v.y); l.y = tf32r(v.y - h.y);
    h.z = tf32r(v.z); l.z = tf32r(v.z - h.z);
    h.w = tf32r(v.w); l.w = tf32r(v.w - h.w);
    hi[i] = h; lo[i] = l;
}

__global__ void round_kernel(const float4* __restrict__ src, float4* __restrict__ dst, int n4) {
    int i = blockIdx.x * blockDim.x + threadIdx.x;
    if (i >= n4) return;
    float4 v = src[i];
    float4 h;
    h.x = tf32r(v.x); h.y = tf32r(v.y); h.z = tf32r(v.z); h.w = tf32r(v.w);
    dst[i] = h;
}

// ---------------- 2xTF32 pipelined GEMM: C[m,n] = sum_k A[m,k]*B[n,k] ----------------
// Operands pre-converted in gmem: Ah/Al = tf32 hi/lo planes, Bt = tf32-rounded weights.
// 3-stage cp.async pipeline, one __syncthreads per k-tile.
#define GBM 128
#define GBN 128
#define GBK 16
#define G_STR 20
#define STG_AL (128 * G_STR)          // float offset of A-lo within a stage
#define STG_B  (256 * G_STR)          // float offset of B within a stage
#define STG_SZ (3 * 128 * G_STR)      // floats per stage = 7680
#define GEMM_SMEM (3 * STG_SZ * 4)    // 92160 B

template<int ROPE, int TFOUT>
__global__ __launch_bounds__(256, 2)
void gemm_pl(const float* __restrict__ Ah, const float* __restrict__ Al,
             const float* __restrict__ Bt, float* __restrict__ C,
             const int* __restrict__ pos) {
    extern __shared__ float sm[];
    const uint32_t smem_base = (uint32_t)__cvta_generic_to_shared(sm);

    const int tid = threadIdx.x;
    const int m0 = blockIdx.y * GBM;
    const int n0 = blockIdx.x * GBN;
    const int w = tid >> 5, lane = tid & 31;
    const int g = lane >> 2, t4 = lane & 3;
    const int wm = w >> 1, wn = w & 1;     // 4x2 warp grid, warp tile 32x64

    float acc[2][8][4];
#pragma unroll
    for (int i = 0; i < 2; i++)
#pragma unroll
        for (int j = 0; j < 8; j++)
#pragma unroll
            for (int e = 0; e < 4; e++) acc[i][j][e] = 0.f;

    auto issue = [&](int t) {
        int k0 = t * GBK;
        uint32_t base = smem_base + (uint32_t)((t % 3) * STG_SZ) * 4;
#pragma unroll
        for (int it = 0; it < 2; it++) {
            int idx = tid + it * 256;
            int row = idx >> 2;
            int c4  = idx & 3;
            size_t goA = (size_t)(m0 + row) * D_MODEL + k0 + c4 * 4;
            size_t goB = (size_t)(n0 + row) * D_MODEL + k0 + c4 * 4;
            uint32_t so = (uint32_t)(row * G_STR + c4 * 4) * 4;
            cp_async16(base + so, Ah + goA);
            cp_async16(base + STG_AL * 4 + so, Al + goA);
            cp_async16(base + STG_B * 4 + so, Bt + goB);
        }
        cp_commit();
    };

    const int NT = D_MODEL / GBK;   // 64
    issue(0);
    issue(1);

    for (int t = 0; t < NT; t++) {
        if (t + 1 < NT) cp_wait<1>(); else cp_wait<0>();
        __syncthreads();

        const float* As  = sm + (t % 3) * STG_SZ;
        const float* Als = As + STG_AL;
        const float* Bs  = As + STG_B;

#pragma unroll
        for (int kk = 0; kk < GBK; kk += 8) {
            uint32_t ah[2][4], al[2][4];
#pragma unroll
            for (int i = 0; i < 2; i++) {
                int r = (wm * 32 + i * 16 + g) * G_STR + kk + t4;
                ah[i][0] = fau(As[r]);
                ah[i][1] = fau(As[r + 8 * G_STR]);
                ah[i][2] = fau(As[r + 4]);
                ah[i][3] = fau(As[r + 8 * G_STR + 4]);
                al[i][0] = fau(Als[r]);
                al[i][1] = fau(Als[r + 8 * G_STR]);
                al[i][2] = fau(Als[r + 4]);
                al[i][3] = fau(Als[r + 8 * G_STR + 4]);
            }
#pragma unroll
            for (int j = 0; j < 8; j++) {
                int rb = (wn * 64 + j * 8 + g) * G_STR + kk + t4;
                uint32_t bh0 = fau(Bs[rb]);
                uint32_t bh1 = fau(Bs[rb + 4]);
#pragma unroll
                for (int i = 0; i < 2; i++) {
                    mma_tf32(acc[i][j], ah[i], bh0, bh1);
                    mma_tf32(acc[i][j], al[i], bh0, bh1);
                }
            }
        }

        if (t + 2 < NT) issue(t + 2);
    }

    // epilogue; ROPE / TFOUT compile-time
    float invf[8];
    if (ROPE) {
#pragma unroll
        for (int j = 0; j < 8; j++) {
            int p = ((wn * 64 + j * 8 + 2 * t4) & 63) >> 1;
            invf[j] = powf(10000.0f, -(float)(2 * p) / (float)D_K);
        }
    }
#pragma unroll
    for (int i = 0; i < 2; i++) {
        int r1 = m0 + wm * 32 + i * 16 + g;
        int r2 = r1 + 8;
        float p1 = 0.f, p2 = 0.f;
        if (ROPE) { p1 = (float)pos[r1]; p2 = (float)pos[r2]; }
#pragma unroll
        for (int j = 0; j < 8; j++) {
            int c = n0 + wn * 64 + j * 8 + 2 * t4;
            float v0 = acc[i][j][0], v1 = acc[i][j][1];
            float v2 = acc[i][j][2], v3 = acc[i][j][3];
            if (ROPE) {
                float s, cs;
                sincosf(p1 * invf[j], &s, &cs);
                float u0 = v0 * cs - v1 * s, u1 = v0 * s + v1 * cs;
                v0 = u0; v1 = u1;
                sincosf(p2 * invf[j], &s, &cs);
                float u2 = v2 * cs - v3 * s, u3 = v2 * s + v3 * cs;
                v2 = u2; v3 = u3;
            }
            if (TFOUT) {
                v0 = tf32r(v0); v1 = tf32r(v1); v2 = tf32r(v2); v3 = tf32r(v3);
            }
            *reinterpret_cast<float2*>(&C[(size_t)r1 * D_MODEL + c]) = make_float2(v0, v1);
            *reinterpret_cast<float2*>(&C[(size_t)r2 * D_MODEL + c]) = make_float2(v2, v3);
        }
    }
}

// ============ Flash attention, tf32 mma, cp.async double-buffered K/V (R8-proven) ============
#define AQ 128
#define AK 64
#define KS_STR 68
#define V_STR  72
#define PS_STR 68
#define K_STAGE (AK * KS_STR)
#define V_STAGE (AK * V_STR)
#define ATTN_SMEM ((2 * K_STAGE + 2 * V_STAGE + AQ * PS_STR) * 4)

__global__ __launch_bounds__(256, 2)
void attn_mma_kernel(const float* __restrict__ Q, const float* __restrict__ K,
                     const float* __restrict__ V, float* __restrict__ O) {
    extern __shared__ float sm[];
    float* Kb = sm;                        // 2 stages [64][68]
    float* Vb = sm + 2 * K_STAGE;          // 2 stages [64][72]
    float* Ps = sm + 2 * K_STAGE + 2 * V_STAGE;  // [128][68]

    const int h   = blockIdx.y;
    const int q0  = (gridDim.x - 1 - blockIdx.x) * AQ;  // big CTAs first
    const int tid = threadIdx.x;
    const int w = tid >> 5, lane = tid & 31;
    const int g = lane >> 2, t4 = lane & 3;
    const int wrow = q0 + w * 16;

    const uint32_t smem_base = (uint32_t)__cvta_generic_to_shared(sm);
    const int lr  = tid >> 4;
    const int lc4 = tid & 15;

    uint32_t qh[8][4];
    {
        const float* qb = Q + (size_t)wrow * D_MODEL + h * D_K;
#pragma unroll
        for (int kc = 0; kc < 8; kc++) {
            int c0 = kc * 8 + t4;
            qh[kc][0] = fau(tf32r(qb[(size_t)g * D_MODEL + c0] * 0.125f));
            qh[kc][1] = fau(tf32r(qb[(size_t)(g + 8) * D_MODEL + c0] * 0.125f));
            qh[kc][2] = fau(tf32r(qb[(size_t)g * D_MODEL + c0 + 4] * 0.125f));
            qh[kc][3] = fau(tf32r(qb[(size_t)(g + 8) * D_MODEL + c0 + 4] * 0.125f));
        }
    }

    float o[8][4];
#pragma unroll
    for (int j = 0; j < 8; j++)
#pragma unroll
        for (int e = 0; e < 4; e++) o[j][e] = 0.f;
    float m_a = -1e30f, m_b = -1e30f, l_a = 0.f, l_b = 0.f;

    const int nt = (q0 + AQ) / AK;

    auto issue_tile = [&](int t) {
        int kv0 = t * AK;
        int st  = t & 1;
        uint32_t kdst = smem_base + (st * K_STAGE) * 4;
        uint32_t vdst = smem_base + (2 * K_STAGE + st * V_STAGE) * 4;
#pragma unroll
        for (int it = 0; it < 4; it++) {
            int r  = lr + it * 16;
            const float* kg = &K[(size_t)(kv0 + r) * D_MODEL + h * D_K + lc4 * 4];
            const float* vg = &V[(size_t)(kv0 + r) * D_MODEL + h * D_K + lc4 * 4];
            cp_async16(kdst + (r * KS_STR + lc4 * 4) * 4, kg);
            cp_async16(vdst + (r * V_STR + lc4 * 4) * 4, vg);
        }
        cp_commit();
    };

    issue_tile(0);

    for (int t = 0; t < nt; t++) {
        if (t + 1 < nt) {
            issue_tile(t + 1);
            cp_wait<1>();
        } else {
            cp_wait<0>();
        }
        __syncthreads();

        const int kv0 = t * AK;
        const float* Ks = Kb + (t & 1) * K_STAGE;
        const float* Vs = Vb + (t & 1) * V_STAGE;

        if (kv0 <= wrow + 15) {
            float s[8][4];
#pragma unroll
            for (int j = 0; j < 8; j++)
#pragma unroll
                for (int e = 0; e < 4; e++) s[j][e] = 0.f;

#pragma unroll
            for (int kc = 0; kc < 8; kc++) {
#pragma unroll
                for (int j = 0; j < 8; j++) {
                    int rb = (j * 8 + g) * KS_STR + kc * 8 + t4;
                    uint32_t b0 = fau(Ks[rb]);
                    uint32_t b1 = fau(Ks[rb + 4]);
                    mma_tf32(s[j], qh[kc], b0, b1);
                }
            }

            if (kv0 + AK - 1 > wrow) {
#pragma unroll
                for (int j = 0; j < 8; j++) {
                    int col = kv0 + j * 8 + 2 * t4;
                    int ra = wrow + g, rb2 = wrow + g + 8;
                    if (col > ra)      s[j][0] = -1e30f;
                    if (col + 1 > ra)  s[j][1] = -1e30f;
                    if (col > rb2)     s[j][2] = -1e30f;
                    if (col + 1 > rb2) s[j][3] = -1e30f;
                }
            }

            float mx_a = -1e30f, mx_b = -1e30f;
#pragma unroll
            for (int j = 0; j < 8; j++) {
                mx_a = fmaxf(mx_a, fmaxf(s[j][0], s[j][1]));
                mx_b = fmaxf(mx_b, fmaxf(s[j][2], s[j][3]));
            }
            mx_a = fmaxf(mx_a, __shfl_xor_sync(0xffffffffu, mx_a, 1));
            mx_a = fmaxf(mx_a, __shfl_xor_sync(0xffffffffu, mx_a, 2));
            mx_b = fmaxf(mx_b, __shfl_xor_sync(0xffffffffu, mx_b, 1));
            mx_b = fmaxf(mx_b, __shfl_xor_sync(0xffffffffu, mx_b, 2));
            float nm_a = fmaxf(m_a, mx_a), nm_b = fmaxf(m_b, mx_b);
            float al_a = __expf(m_a - nm_a), al_b = __expf(m_b - nm_b);
            m_a = nm_a; m_b = nm_b;

            float sum_a = 0.f, sum_b = 0.f;
#pragma unroll
            for (int j = 0; j < 8; j++) {
                float p0 = __expf(s[j][0] - m_a);
                float p1 = __expf(s[j][1] - m_a);
                float p2 = __expf(s[j][2] - m_b);
                float p3 = __expf(s[j][3] - m_b);
                sum_a += p0 + p1;
                sum_b += p2 + p3;
                o[j][0] *= al_a; o[j][1] *= al_a;
                o[j][2] *= al_b; o[j][3] *= al_b;
                float2 pa = make_float2(tf32r(p0), tf32r(p1));
                float2 pb = make_float2(tf32r(p2), tf32r(p3));
                *reinterpret_cast<float2*>(&Ps[(w * 16 + g) * PS_STR + j * 8 + 2 * t4]) = pa;
                *reinterpret_cast<float2*>(&Ps[(w * 16 + g + 8) * PS_STR + j * 8 + 2 * t4]) = pb;
            }
            sum_a += __shfl_xor_sync(0xffffffffu, sum_a, 1);
            sum_a += __shfl_xor_sync(0xffffffffu, sum_a, 2);
            sum_b += __shfl_xor_sync(0xffffffffu, sum_b, 1);
            sum_b += __shfl_xor_sync(0xffffffffu, sum_b, 2);
            l_a = l_a * al_a + sum_a;
            l_b = l_b * al_b + sum_b;
            __syncwarp();

#pragma unroll
            for (int kc = 0; kc < 8; kc++) {
                uint32_t pa[4];
                int pr = (w * 16 + g) * PS_STR + kc * 8 + t4;
                pa[0] = fau(Ps[pr]);
                pa[1] = fau(Ps[pr + 8 * PS_STR]);
                pa[2] = fau(Ps[pr + 4]);
                pa[3] = fau(Ps[pr + 8 * PS_STR + 4]);
#pragma unroll
                for (int j = 0; j < 8; j++) {
                    int vb = (kc * 8 + t4) * V_STR + j * 8 + g;
                    uint32_t b0 = fau(Vs[vb]);
                    uint32_t b1 = fau(Vs[vb + 4 * V_STR]);
                    mma_tf32(o[j], pa, b0, b1);
                }
            }
        }
        __syncthreads();
    }

    float ia = 1.0f / l_a, ib = 1.0f / l_b;
#pragma unroll
    for (int j = 0; j < 8; j++) {
        int c = h * D_K + j * 8 + 2 * t4;
        float2 v0 = make_float2(o[j][0] * ia, o[j][1] * ia);
        float2 v1 = make_float2(o[j][2] * ib, o[j][3] * ib);
        *reinterpret_cast<float2*>(&O[(size_t)(wrow + g) * D_MODEL + c]) = v0;
        *reinterpret_cast<float2*>(&O[(size_t)(wrow + g + 8) * D_MODEL + c]) = v1;
    }
}

// ---------------- launcher ----------------
extern "C" void kernel_launch(void* const* d_in, const int* in_sizes, int n_in,
                              void* d_out, int out_size) {
    const float* x  = (const float*)d_in[0];
    const float* Wq = (const float*)d_in[1];
    const float* Wk = (const float*)d_in[2];
    const float* Wv = (const float*)d_in[3];
    const float* Wo = (const float*)d_in[4];
    const int*  pos = (const int*)d_in[5];
    float* out = (float*)d_out;

    float *Qp, *Kp, *Vp, *Ap, *XH, *XL, *Wr;
    cudaGetSymbolAddress((void**)&Qp, g_Q);
    cudaGetSymbolAddress((void**)&Kp, g_K);
    cudaGetSymbolAddress((void**)&Vp, g_V);
    cudaGetSymbolAddress((void**)&Ap, g_AT);
    cudaGetSymbolAddress((void**)&XH, g_XH);
    cudaGetSymbolAddress((void**)&XL, g_XL);
    cudaGetSymbolAddress((void**)&Wr, g_W);

    cudaFuncSetAttribute(gemm_pl<1,0>, cudaFuncAttributeMaxDynamicSharedMemorySize, GEMM_SMEM);
    cudaFuncSetAttribute(gemm_pl<1,1>, cudaFuncAttributeMaxDynamicSharedMemorySize, GEMM_SMEM);
    cudaFuncSetAttribute(gemm_pl<0,1>, cudaFuncAttributeMaxDynamicSharedMemorySize, GEMM_SMEM);
    cudaFuncSetAttribute(gemm_pl<0,0>, cudaFuncAttributeMaxDynamicSharedMemorySize, GEMM_SMEM);
    cudaFuncSetAttribute(attn_mma_kernel, cudaFuncAttributeMaxDynamicSharedMemorySize, ATTN_SMEM);

    const int NX4 = S_LEN * D_MODEL / 4;     // 1M float4
    const int NW4 = D_MODEL * D_MODEL / 4;   // 256K float4
    dim3 ggrid(D_MODEL / GBN, S_LEN / GBM);  // (8, 32)
    dim3 agrid(S_LEN / AQ, NUM_HEADS);       // (32, 16)

    // split activations once
    split_kernel<<<(NX4 + 255) / 256, 256>>>((const float4*)x, (float4*)XH, (float4*)XL, NX4);

    // Q projection (+RoPE)
    round_kernel<<<(NW4 + 255) / 256, 256>>>((const float4*)Wq, (float4*)Wr, NW4);
    gemm_pl<1,0><<<ggrid, 256, GEMM_SMEM>>>(XH, XL, Wr, Qp, pos);

    // K projection (+RoPE, tf32 out)
    round_kernel<<<(NW4 + 255) / 256, 256>>>((const float4*)Wk, (float4*)Wr, NW4);
    gemm_pl<1,1><<<ggrid, 256, GEMM_SMEM>>>(XH, XL, Wr, Kp, pos);

    // V projection (tf32 out)
    round_kernel<<<(NW4 + 255) / 256, 256>>>((const float4*)Wv, (float4*)Wr, NW4);
    gemm_pl<0,1><<<ggrid, 256, GEMM_SMEM>>>(XH, XL, Wr, Vp, pos);

    // attention
    attn_mma_kernel<<<agrid, 256, ATTN_SMEM>>>(Qp, Kp, Vp, Ap);

    // O projection: split attn output (reuse XH/XL), round Wo
    split_kernel<<<(NX4 + 255) / 256, 256>>>((const float4*)Ap, (float4*)XH, (float4*)XL, NX4);
    round_kernel<<<(NW4 + 255) / 256, 256>>>((const float4*)Wo, (float4*)Wr, NW4);
    gemm_pl<0,0><<<ggrid, 256, GEMM_SMEM>>>(XH, XL, Wr, out, pos);
}